// round 1
// baseline (speedup 1.0000x reference)
#include <cuda_runtime.h>
#include <math.h>

// Problem constants
//  x:       [12, 1024, 1024] f32   -> viewed as [2, 6144, 1024]
//  context: [2, 1024, 1024]  f32
//  Wq/Wk/Wv/Wo: [1024,1024] f32, bo: [1024]
//  out:     [12, 1024, 1024] f32 == [2, 6144, 1024]
#define DMODEL 1024
#define NHEADS 16
#define DHEAD  64
#define SQ_TOT 6144   // per batch
#define SK_TOT 1024
#define BATCH  2

// Scratch (allocation-free rule: __device__ globals)
__device__ float g_Q[BATCH * SQ_TOT * DMODEL];   // [b, sq, h*64+d]
__device__ float g_K[BATCH * SK_TOT * DMODEL];
__device__ float g_V[BATCH * SK_TOT * DMODEL];
__device__ float g_A[BATCH * SQ_TOT * DMODEL];   // attention output, same layout as Q

// ---------------------------------------------------------------------------
// SGEMM NT: C[m,n] = sum_k A[m,k] * B[n,k] (+ bias[n])
// BM=BN=128, BK=8, 256 threads, 8x8 micro-tile per thread.
// ---------------------------------------------------------------------------
__global__ __launch_bounds__(256) void sgemm_nt(
    const float* __restrict__ A, const float* __restrict__ B,
    float* __restrict__ C, int M, int N, int K, const float* __restrict__ bias)
{
    const int BM = 128, BN = 128, BK = 8;
    __shared__ float As[BK][BM + 4];
    __shared__ float Bs[BK][BN + 4];

    const int bm = blockIdx.y * BM;
    const int bn = blockIdx.x * BN;
    const int tid = threadIdx.x;
    const int tx = tid & 15;        // 0..15 -> N direction
    const int ty = tid >> 4;        // 0..15 -> M direction
    const int lrow = tid >> 1;      // 0..127
    const int lcol = (tid & 1) * 4; // 0 or 4

    const float* Ap = A + (size_t)(bm + lrow) * K + lcol;
    const float* Bp = B + (size_t)(bn + lrow) * K + lcol;

    float acc[8][8];
#pragma unroll
    for (int i = 0; i < 8; i++)
#pragma unroll
        for (int j = 0; j < 8; j++) acc[i][j] = 0.0f;

    for (int k0 = 0; k0 < K; k0 += BK) {
        float4 av = *(const float4*)(Ap + k0);
        float4 bv = *(const float4*)(Bp + k0);
        As[lcol + 0][lrow] = av.x; As[lcol + 1][lrow] = av.y;
        As[lcol + 2][lrow] = av.z; As[lcol + 3][lrow] = av.w;
        Bs[lcol + 0][lrow] = bv.x; Bs[lcol + 1][lrow] = bv.y;
        Bs[lcol + 2][lrow] = bv.z; Bs[lcol + 3][lrow] = bv.w;
        __syncthreads();
#pragma unroll
        for (int kk = 0; kk < BK; kk++) {
            float4 a0 = *(const float4*)&As[kk][ty * 4];
            float4 a1 = *(const float4*)&As[kk][64 + ty * 4];
            float4 b0 = *(const float4*)&Bs[kk][tx * 4];
            float4 b1 = *(const float4*)&Bs[kk][64 + tx * 4];
            float a[8] = {a0.x, a0.y, a0.z, a0.w, a1.x, a1.y, a1.z, a1.w};
            float b[8] = {b0.x, b0.y, b0.z, b0.w, b1.x, b1.y, b1.z, b1.w};
#pragma unroll
            for (int i = 0; i < 8; i++)
#pragma unroll
                for (int j = 0; j < 8; j++)
                    acc[i][j] = fmaf(a[i], b[j], acc[i][j]);
        }
        __syncthreads();
    }

#pragma unroll
    for (int i = 0; i < 8; i++) {
        int r = bm + ((i < 4) ? (ty * 4 + i) : (64 + ty * 4 + (i - 4)));
#pragma unroll
        for (int j = 0; j < 8; j++) {
            int c = bn + ((j < 4) ? (tx * 4 + j) : (64 + tx * 4 + (j - 4)));
            float v = acc[i][j];
            if (bias) v += __ldg(&bias[c]);
            C[(size_t)r * N + c] = v;
        }
    }
}

// ---------------------------------------------------------------------------
// Fused flash-style attention.
// Grid: (SQ_TOT/64, NHEADS, BATCH), block 256 threads.
// Per block: 64 queries x full 1024 keys for one (b,h). d = 64.
// Shared: sQ [d][q] (scale folded in), sK [d][k], sV [k][d], sP [k][q].
// Thread (tx,ty) owns a 4x4 tile (rows ty*4.., cols tx*4..) for both S and O.
// Online softmax state replicated across the 16 tx lanes per row group.
// ---------------------------------------------------------------------------
#define ATT_STRIDE 68
#define ATT_SMEM_BYTES (4 * 64 * ATT_STRIDE * 4)

__global__ __launch_bounds__(256) void attn_kernel(
    const float* __restrict__ Q, const float* __restrict__ K,
    const float* __restrict__ V, float* __restrict__ O)
{
    extern __shared__ float sm[];
    float* sQ = sm;                      // [64][ATT_STRIDE] : [d][q]
    float* sK = sQ + 64 * ATT_STRIDE;    // [d][k]
    float* sV = sK + 64 * ATT_STRIDE;    // [k][d]
    float* sP = sV + 64 * ATT_STRIDE;    // [k][q]

    const int b = blockIdx.z;
    const int h = blockIdx.y;
    const int qt = blockIdx.x;

    const int tid = threadIdx.x;
    const int tx = tid & 15;
    const int ty = tid >> 4;
    const int lr = tid & 63;        // row within 64 for loads
    const int lc = (tid >> 6) * 16; // 16-wide column chunk for loads

    const float scale = 0.125f;     // 1/sqrt(64)

    // Load Q tile transposed into sQ[d][q], folding in the softmax scale.
    {
        const float* qg = Q + ((size_t)(b * SQ_TOT + qt * 64 + lr)) * DMODEL + h * DHEAD + lc;
#pragma unroll
        for (int c = 0; c < 16; c += 4) {
            float4 v = *(const float4*)(qg + c);
            sQ[(lc + c + 0) * ATT_STRIDE + lr] = v.x * scale;
            sQ[(lc + c + 1) * ATT_STRIDE + lr] = v.y * scale;
            sQ[(lc + c + 2) * ATT_STRIDE + lr] = v.z * scale;
            sQ[(lc + c + 3) * ATT_STRIDE + lr] = v.w * scale;
        }
    }

    float m_i[4], l_i[4], o[4][4];
#pragma unroll
    for (int i = 0; i < 4; i++) {
        m_i[i] = -1e30f;
        l_i[i] = 0.0f;
#pragma unroll
        for (int j = 0; j < 4; j++) o[i][j] = 0.0f;
    }

    for (int kt = 0; kt < SK_TOT / 64; kt++) {
        __syncthreads();  // previous iteration's PV reads done before overwrite
        // Load K tile transposed [d][k] and V tile direct [k][d]
        {
            const size_t krow = (size_t)(b * SK_TOT + kt * 64 + lr) * DMODEL + h * DHEAD + lc;
            const float* kg = K + krow;
            const float* vg = V + krow;
#pragma unroll
            for (int c = 0; c < 16; c += 4) {
                float4 kv = *(const float4*)(kg + c);
                sK[(lc + c + 0) * ATT_STRIDE + lr] = kv.x;
                sK[(lc + c + 1) * ATT_STRIDE + lr] = kv.y;
                sK[(lc + c + 2) * ATT_STRIDE + lr] = kv.z;
                sK[(lc + c + 3) * ATT_STRIDE + lr] = kv.w;
                float4 vv = *(const float4*)(vg + c);
                *(float4*)&sV[lr * ATT_STRIDE + lc + c] = vv;
            }
        }
        __syncthreads();

        // S = (scaled Q) @ K^T : 4x4 per thread
        float s[4][4];
#pragma unroll
        for (int i = 0; i < 4; i++)
#pragma unroll
            for (int j = 0; j < 4; j++) s[i][j] = 0.0f;
#pragma unroll
        for (int kk = 0; kk < 64; kk++) {
            float4 a = *(const float4*)&sQ[kk * ATT_STRIDE + ty * 4];
            float4 bb = *(const float4*)&sK[kk * ATT_STRIDE + tx * 4];
            float av[4] = {a.x, a.y, a.z, a.w};
            float bv[4] = {bb.x, bb.y, bb.z, bb.w};
#pragma unroll
            for (int i = 0; i < 4; i++)
#pragma unroll
                for (int j = 0; j < 4; j++)
                    s[i][j] = fmaf(av[i], bv[j], s[i][j]);
        }

        // Online softmax per query row (reduce across the 16 tx lanes)
#pragma unroll
        for (int i = 0; i < 4; i++) {
            float mloc = fmaxf(fmaxf(s[i][0], s[i][1]), fmaxf(s[i][2], s[i][3]));
#pragma unroll
            for (int w = 8; w >= 1; w >>= 1)
                mloc = fmaxf(mloc, __shfl_xor_sync(0xffffffffu, mloc, w));
            float m_new = fmaxf(m_i[i], mloc);
            float alpha = __expf(m_i[i] - m_new);
            m_i[i] = m_new;
            float rs = 0.0f;
#pragma unroll
            for (int j = 0; j < 4; j++) {
                float p = __expf(s[i][j] - m_new);
                s[i][j] = p;
                rs += p;
            }
#pragma unroll
            for (int w = 8; w >= 1; w >>= 1)
                rs += __shfl_xor_sync(0xffffffffu, rs, w);
            l_i[i] = l_i[i] * alpha + rs;
#pragma unroll
            for (int j = 0; j < 4; j++) o[i][j] *= alpha;
            // stage P transposed: sP[k][q]
#pragma unroll
            for (int j = 0; j < 4; j++)
                sP[(tx * 4 + j) * ATT_STRIDE + ty * 4 + i] = s[i][j];
        }
        __syncthreads();

        // O += P @ V : 4x4 per thread (rows = q via ty, cols = d via tx)
#pragma unroll
        for (int kk = 0; kk < 64; kk++) {
            float4 a = *(const float4*)&sP[kk * ATT_STRIDE + ty * 4];
            float4 v0 = *(const float4*)&sV[kk * ATT_STRIDE + tx * 4];
            float av[4] = {a.x, a.y, a.z, a.w};
            float vv[4] = {v0.x, v0.y, v0.z, v0.w};
#pragma unroll
            for (int i = 0; i < 4; i++)
#pragma unroll
                for (int j = 0; j < 4; j++)
                    o[i][j] = fmaf(av[i], vv[j], o[i][j]);
        }
    }

    // Epilogue: normalize and store
    float* og = O + ((size_t)(b * SQ_TOT + qt * 64)) * DMODEL + h * DHEAD;
#pragma unroll
    for (int i = 0; i < 4; i++) {
        float inv = 1.0f / l_i[i];
#pragma unroll
        for (int j = 0; j < 4; j++)
            og[(size_t)(ty * 4 + i) * DMODEL + tx * 4 + j] = o[i][j] * inv;
    }
}

// ---------------------------------------------------------------------------
extern "C" void kernel_launch(void* const* d_in, const int* in_sizes, int n_in,
                              void* d_out, int out_size)
{
    const float* x   = (const float*)d_in[0];
    const float* ctx = (const float*)d_in[1];
    const float* Wq  = (const float*)d_in[2];
    const float* Wk  = (const float*)d_in[3];
    const float* Wv  = (const float*)d_in[4];
    const float* Wo  = (const float*)d_in[5];
    const float* bo  = (const float*)d_in[6];
    float* out = (float*)d_out;

    float *qb, *kb, *vb, *ab;
    cudaGetSymbolAddress((void**)&qb, g_Q);
    cudaGetSymbolAddress((void**)&kb, g_K);
    cudaGetSymbolAddress((void**)&vb, g_V);
    cudaGetSymbolAddress((void**)&ab, g_A);

    cudaFuncSetAttribute(attn_kernel,
                         cudaFuncAttributeMaxDynamicSharedMemorySize,
                         ATT_SMEM_BYTES);

    const int M_Q = BATCH * SQ_TOT;   // 12288
    const int M_KV = BATCH * SK_TOT;  // 2048

    // Projections
    sgemm_nt<<<dim3(DMODEL / 128, M_Q / 128), 256>>>(x,   Wq, qb, M_Q,  DMODEL, DMODEL, nullptr);
    sgemm_nt<<<dim3(DMODEL / 128, M_KV / 128), 256>>>(ctx, Wk, kb, M_KV, DMODEL, DMODEL, nullptr);
    sgemm_nt<<<dim3(DMODEL / 128, M_KV / 128), 256>>>(ctx, Wv, vb, M_KV, DMODEL, DMODEL, nullptr);

    // Attention
    attn_kernel<<<dim3(SQ_TOT / 64, NHEADS, BATCH), 256, ATT_SMEM_BYTES>>>(qb, kb, vb, ab);

    // Output projection (+bias) straight into d_out
    sgemm_nt<<<dim3(DMODEL / 128, M_Q / 128), 256>>>(ab, Wo, out, M_Q, DMODEL, DMODEL, bo);
}

// round 3
// speedup vs baseline: 1.3759x; 1.3759x over previous
#include <cuda_runtime.h>
#include <cstdint>
#include <math.h>

// Problem constants
#define DMODEL 1024
#define NHEADS 16
#define DHEAD  64
#define SQ_TOT 6144   // per batch
#define SK_TOT 1024
#define BATCH  2

// Scratch (allocation-free rule: __device__ globals)
__device__ float g_Q[BATCH * SQ_TOT * DMODEL];
__device__ float g_K[BATCH * SK_TOT * DMODEL];
__device__ float g_V[BATCH * SK_TOT * DMODEL];
__device__ float g_A[BATCH * SQ_TOT * DMODEL];

__device__ __forceinline__ uint32_t f2tf32(float x) {
    uint32_t u;
    asm("cvt.rna.tf32.f32 %0, %1;" : "=r"(u) : "f"(x));
    return u;
}

// ===========================================================================
// tf32 mma.sync GEMM NT:  C[m,n] = sum_k A[m,k]*B[n,k] (+ bias[n])
// CTA 128x128, 256 threads = 8 warps (2 M x 4 N), warp tile 64x32.
// K-chunk 16, double-buffered smem, stride-20 padding (bank-conflict-free
// for the m16n8k8 fragment pattern: g*20 + t hits all 32 banks once).
// ===========================================================================
#define KC 16
#define SA 20   // smem row stride in floats

__global__ __launch_bounds__(256) void gemm_mma(
    const float* __restrict__ A, const float* __restrict__ B,
    float* __restrict__ C, int M, int N, int K, const float* __restrict__ bias)
{
    __shared__ uint32_t As[2][128 * SA];
    __shared__ uint32_t Bs[2][128 * SA];

    const int tid = threadIdx.x;
    const int wid = tid >> 5;
    const int lane = tid & 31;
    const int g = lane >> 2;      // groupID 0..7
    const int t = lane & 3;       // thread-in-group 0..3
    const int wm = (wid & 1) * 64;    // warp M offset in CTA tile
    const int wn = (wid >> 1) * 32;   // warp N offset
    const int bm = blockIdx.y * 128;
    const int bn = blockIdx.x * 128;

    // Global load mapping: thread -> row tid/2, two float4s (cols 0..7 or 8..15)
    const int lrow = tid >> 1;
    const int lc4 = (tid & 1) * 2;   // float4 index 0 or 2
    const float* Ag = A + (size_t)(bm + lrow) * K + lc4 * 4;
    const float* Bg = B + (size_t)(bn + lrow) * K + lc4 * 4;

    float4 ra[2], rb[2];

    float acc[4][4][4];
#pragma unroll
    for (int i = 0; i < 4; i++)
#pragma unroll
        for (int j = 0; j < 4; j++)
#pragma unroll
            for (int r = 0; r < 4; r++) acc[i][j][r] = 0.0f;

    const int NC = K / KC;

    // prefetch chunk 0
#pragma unroll
    for (int j = 0; j < 2; j++) {
        ra[j] = *(const float4*)(Ag + j * 4);
        rb[j] = *(const float4*)(Bg + j * 4);
    }
    {
        const int si = lrow * SA + lc4 * 4;
#pragma unroll
        for (int j = 0; j < 2; j++) {
            As[0][si + j * 4 + 0] = f2tf32(ra[j].x);
            As[0][si + j * 4 + 1] = f2tf32(ra[j].y);
            As[0][si + j * 4 + 2] = f2tf32(ra[j].z);
            As[0][si + j * 4 + 3] = f2tf32(ra[j].w);
            Bs[0][si + j * 4 + 0] = f2tf32(rb[j].x);
            Bs[0][si + j * 4 + 1] = f2tf32(rb[j].y);
            Bs[0][si + j * 4 + 2] = f2tf32(rb[j].z);
            Bs[0][si + j * 4 + 3] = f2tf32(rb[j].w);
        }
    }
    __syncthreads();

    for (int c = 0; c < NC; c++) {
        const int buf = c & 1;
        if (c + 1 < NC) {
            const size_t off = (size_t)(c + 1) * KC;
#pragma unroll
            for (int j = 0; j < 2; j++) {
                ra[j] = *(const float4*)(Ag + off + j * 4);
                rb[j] = *(const float4*)(Bg + off + j * 4);
            }
        }

        // compute on buf
#pragma unroll
        for (int ks = 0; ks < KC; ks += 8) {
            uint32_t af[4][4];
            uint32_t bf[4][2];
#pragma unroll
            for (int mt = 0; mt < 4; mt++) {
                const int r0 = (wm + mt * 16 + g) * SA + ks + t;
                af[mt][0] = As[buf][r0];
                af[mt][1] = As[buf][r0 + 8 * SA];
                af[mt][2] = As[buf][r0 + 4];
                af[mt][3] = As[buf][r0 + 8 * SA + 4];
            }
#pragma unroll
            for (int nt = 0; nt < 4; nt++) {
                const int r0 = (wn + nt * 8 + g) * SA + ks + t;
                bf[nt][0] = Bs[buf][r0];
                bf[nt][1] = Bs[buf][r0 + 4];
            }
#pragma unroll
            for (int mt = 0; mt < 4; mt++)
#pragma unroll
                for (int nt = 0; nt < 4; nt++) {
                    asm volatile(
                        "mma.sync.aligned.m16n8k8.row.col.f32.tf32.tf32.f32 "
                        "{%0,%1,%2,%3}, {%4,%5,%6,%7}, {%8,%9}, {%0,%1,%2,%3};"
                        : "+f"(acc[mt][nt][0]), "+f"(acc[mt][nt][1]),
                          "+f"(acc[mt][nt][2]), "+f"(acc[mt][nt][3])
                        : "r"(af[mt][0]), "r"(af[mt][1]),
                          "r"(af[mt][2]), "r"(af[mt][3]),
                          "r"(bf[nt][0]), "r"(bf[nt][1]));
                }
        }

        if (c + 1 < NC) {
            const int nb = (c + 1) & 1;
            const int si = lrow * SA + lc4 * 4;
#pragma unroll
            for (int j = 0; j < 2; j++) {
                As[nb][si + j * 4 + 0] = f2tf32(ra[j].x);
                As[nb][si + j * 4 + 1] = f2tf32(ra[j].y);
                As[nb][si + j * 4 + 2] = f2tf32(ra[j].z);
                As[nb][si + j * 4 + 3] = f2tf32(ra[j].w);
                Bs[nb][si + j * 4 + 0] = f2tf32(rb[j].x);
                Bs[nb][si + j * 4 + 1] = f2tf32(rb[j].y);
                Bs[nb][si + j * 4 + 2] = f2tf32(rb[j].z);
                Bs[nb][si + j * 4 + 3] = f2tf32(rb[j].w);
            }
            __syncthreads();
        }
    }

    // Epilogue: per tile, thread owns (g, t*2) and (g+8, t*2) float2 pairs
#pragma unroll
    for (int mt = 0; mt < 4; mt++) {
#pragma unroll
        for (int nt = 0; nt < 4; nt++) {
            const int row = bm + wm + mt * 16 + g;
            const int col = bn + wn + nt * 8 + t * 2;
            float2 v0 = make_float2(acc[mt][nt][0], acc[mt][nt][1]);
            float2 v1 = make_float2(acc[mt][nt][2], acc[mt][nt][3]);
            if (bias) {
                float2 bv = *(const float2*)&bias[col];
                v0.x += bv.x; v0.y += bv.y;
                v1.x += bv.x; v1.y += bv.y;
            }
            *(float2*)&C[(size_t)row * N + col] = v0;
            *(float2*)&C[(size_t)(row + 8) * N + col] = v1;
        }
    }
}

// ===========================================================================
// Fused flash-style attention (unchanged — next round's target).
// ===========================================================================
#define ATT_STRIDE 68
#define ATT_SMEM_BYTES (4 * 64 * ATT_STRIDE * 4)

__global__ __launch_bounds__(256) void attn_kernel(
    const float* __restrict__ Q, const float* __restrict__ K,
    const float* __restrict__ V, float* __restrict__ O)
{
    extern __shared__ float sm[];
    float* sQ = sm;
    float* sK = sQ + 64 * ATT_STRIDE;
    float* sV = sK + 64 * ATT_STRIDE;
    float* sP = sV + 64 * ATT_STRIDE;

    const int b = blockIdx.z;
    const int h = blockIdx.y;
    const int qt = blockIdx.x;

    const int tid = threadIdx.x;
    const int tx = tid & 15;
    const int ty = tid >> 4;
    const int lr = tid & 63;
    const int lc = (tid >> 6) * 16;

    const float scale = 0.125f;

    {
        const float* qg = Q + ((size_t)(b * SQ_TOT + qt * 64 + lr)) * DMODEL + h * DHEAD + lc;
#pragma unroll
        for (int c = 0; c < 16; c += 4) {
            float4 v = *(const float4*)(qg + c);
            sQ[(lc + c + 0) * ATT_STRIDE + lr] = v.x * scale;
            sQ[(lc + c + 1) * ATT_STRIDE + lr] = v.y * scale;
            sQ[(lc + c + 2) * ATT_STRIDE + lr] = v.z * scale;
            sQ[(lc + c + 3) * ATT_STRIDE + lr] = v.w * scale;
        }
    }

    float m_i[4], l_i[4], o[4][4];
#pragma unroll
    for (int i = 0; i < 4; i++) {
        m_i[i] = -1e30f;
        l_i[i] = 0.0f;
#pragma unroll
        for (int j = 0; j < 4; j++) o[i][j] = 0.0f;
    }

    for (int kt = 0; kt < SK_TOT / 64; kt++) {
        __syncthreads();
        {
            const size_t krow = (size_t)(b * SK_TOT + kt * 64 + lr) * DMODEL + h * DHEAD + lc;
            const float* kg = K + krow;
            const float* vg = V + krow;
#pragma unroll
            for (int c = 0; c < 16; c += 4) {
                float4 kv = *(const float4*)(kg + c);
                sK[(lc + c + 0) * ATT_STRIDE + lr] = kv.x;
                sK[(lc + c + 1) * ATT_STRIDE + lr] = kv.y;
                sK[(lc + c + 2) * ATT_STRIDE + lr] = kv.z;
                sK[(lc + c + 3) * ATT_STRIDE + lr] = kv.w;
                float4 vv = *(const float4*)(vg + c);
                *(float4*)&sV[lr * ATT_STRIDE + lc + c] = vv;
            }
        }
        __syncthreads();

        float s[4][4];
#pragma unroll
        for (int i = 0; i < 4; i++)
#pragma unroll
            for (int j = 0; j < 4; j++) s[i][j] = 0.0f;
#pragma unroll
        for (int kk = 0; kk < 64; kk++) {
            float4 a = *(const float4*)&sQ[kk * ATT_STRIDE + ty * 4];
            float4 bb = *(const float4*)&sK[kk * ATT_STRIDE + tx * 4];
            float av[4] = {a.x, a.y, a.z, a.w};
            float bv[4] = {bb.x, bb.y, bb.z, bb.w};
#pragma unroll
            for (int i = 0; i < 4; i++)
#pragma unroll
                for (int j = 0; j < 4; j++)
                    s[i][j] = fmaf(av[i], bv[j], s[i][j]);
        }

#pragma unroll
        for (int i = 0; i < 4; i++) {
            float mloc = fmaxf(fmaxf(s[i][0], s[i][1]), fmaxf(s[i][2], s[i][3]));
#pragma unroll
            for (int w = 8; w >= 1; w >>= 1)
                mloc = fmaxf(mloc, __shfl_xor_sync(0xffffffffu, mloc, w));
            float m_new = fmaxf(m_i[i], mloc);
            float alpha = __expf(m_i[i] - m_new);
            m_i[i] = m_new;
            float rs = 0.0f;
#pragma unroll
            for (int j = 0; j < 4; j++) {
                float p = __expf(s[i][j] - m_new);
                s[i][j] = p;
                rs += p;
            }
#pragma unroll
            for (int w = 8; w >= 1; w >>= 1)
                rs += __shfl_xor_sync(0xffffffffu, rs, w);
            l_i[i] = l_i[i] * alpha + rs;
#pragma unroll
            for (int j = 0; j < 4; j++) o[i][j] *= alpha;
#pragma unroll
            for (int j = 0; j < 4; j++)
                sP[(tx * 4 + j) * ATT_STRIDE + ty * 4 + i] = s[i][j];
        }
        __syncthreads();

#pragma unroll
        for (int kk = 0; kk < 64; kk++) {
            float4 a = *(const float4*)&sP[kk * ATT_STRIDE + ty * 4];
            float4 v0 = *(const float4*)&sV[kk * ATT_STRIDE + tx * 4];
            float av[4] = {a.x, a.y, a.z, a.w};
            float vv[4] = {v0.x, v0.y, v0.z, v0.w};
#pragma unroll
            for (int i = 0; i < 4; i++)
#pragma unroll
                for (int j = 0; j < 4; j++)
                    o[i][j] = fmaf(av[i], vv[j], o[i][j]);
        }
    }

    float* og = O + ((size_t)(b * SQ_TOT + qt * 64)) * DMODEL + h * DHEAD;
#pragma unroll
    for (int i = 0; i < 4; i++) {
        float inv = 1.0f / l_i[i];
#pragma unroll
        for (int j = 0; j < 4; j++)
            og[(size_t)(ty * 4 + i) * DMODEL + tx * 4 + j] = o[i][j] * inv;
    }
}

// ===========================================================================
extern "C" void kernel_launch(void* const* d_in, const int* in_sizes, int n_in,
                              void* d_out, int out_size)
{
    const float* x   = (const float*)d_in[0];
    const float* ctx = (const float*)d_in[1];
    const float* Wq  = (const float*)d_in[2];
    const float* Wk  = (const float*)d_in[3];
    const float* Wv  = (const float*)d_in[4];
    const float* Wo  = (const float*)d_in[5];
    const float* bo  = (const float*)d_in[6];
    float* out = (float*)d_out;

    float *qb, *kb, *vb, *ab;
    cudaGetSymbolAddress((void**)&qb, g_Q);
    cudaGetSymbolAddress((void**)&kb, g_K);
    cudaGetSymbolAddress((void**)&vb, g_V);
    cudaGetSymbolAddress((void**)&ab, g_A);

    cudaFuncSetAttribute(attn_kernel,
                         cudaFuncAttributeMaxDynamicSharedMemorySize, ATT_SMEM_BYTES);

    const int M_Q = BATCH * SQ_TOT;   // 12288
    const int M_KV = BATCH * SK_TOT;  // 2048

    gemm_mma<<<dim3(DMODEL / 128, M_Q / 128), 256>>>(
        x, Wq, qb, M_Q, DMODEL, DMODEL, nullptr);
    gemm_mma<<<dim3(DMODEL / 128, M_KV / 128), 256>>>(
        ctx, Wk, kb, M_KV, DMODEL, DMODEL, nullptr);
    gemm_mma<<<dim3(DMODEL / 128, M_KV / 128), 256>>>(
        ctx, Wv, vb, M_KV, DMODEL, DMODEL, nullptr);

    attn_kernel<<<dim3(SQ_TOT / 64, NHEADS, BATCH), 256, ATT_SMEM_BYTES>>>(qb, kb, vb, ab);

    gemm_mma<<<dim3(DMODEL / 128, M_Q / 128), 256>>>(
        ab, Wo, out, M_Q, DMODEL, DMODEL, bo);
}

// round 4
// speedup vs baseline: 2.8535x; 2.0740x over previous
#include <cuda_runtime.h>
#include <cstdint>
#include <math.h>

// Problem constants
#define DMODEL 1024
#define NHEADS 16
#define DHEAD  64
#define SQ_TOT 6144   // per batch
#define SK_TOT 1024
#define BATCH  2

// Scratch (allocation-free rule: __device__ globals)
__device__ float g_Q[BATCH * SQ_TOT * DMODEL];
__device__ float g_K[BATCH * SK_TOT * DMODEL];
__device__ float g_V[BATCH * SK_TOT * DMODEL];
__device__ float g_A[BATCH * SQ_TOT * DMODEL];

__device__ __forceinline__ uint32_t f2tf32(float x) {
    uint32_t u;
    asm("cvt.rna.tf32.f32 %0, %1;" : "=r"(u) : "f"(x));
    return u;
}

#define MMA_TF32(d, a0, a1, a2, a3, b0, b1) \
    asm volatile( \
        "mma.sync.aligned.m16n8k8.row.col.f32.tf32.tf32.f32 " \
        "{%0,%1,%2,%3}, {%4,%5,%6,%7}, {%8,%9}, {%0,%1,%2,%3};" \
        : "+f"((d)[0]), "+f"((d)[1]), "+f"((d)[2]), "+f"((d)[3]) \
        : "r"(a0), "r"(a1), "r"(a2), "r"(a3), "r"(b0), "r"(b1))

// ===========================================================================
// tf32 mma.sync GEMM NT:  C[m,n] = scale * sum_k A[m,k]*B[n,k] (+ bias[n])
// CTA 128x128, 256 threads = 8 warps (2 M x 4 N), warp tile 64x32.
// ===========================================================================
#define KC 16
#define SA 20

__global__ __launch_bounds__(256) void gemm_mma(
    const float* __restrict__ A, const float* __restrict__ B,
    float* __restrict__ C, int M, int N, int K,
    const float* __restrict__ bias, float scale)
{
    __shared__ uint32_t As[2][128 * SA];
    __shared__ uint32_t Bs[2][128 * SA];

    const int tid = threadIdx.x;
    const int wid = tid >> 5;
    const int lane = tid & 31;
    const int g = lane >> 2;
    const int t = lane & 3;
    const int wm = (wid & 1) * 64;
    const int wn = (wid >> 1) * 32;
    const int bm = blockIdx.y * 128;
    const int bn = blockIdx.x * 128;

    const int lrow = tid >> 1;
    const int lc4 = (tid & 1) * 2;
    const float* Ag = A + (size_t)(bm + lrow) * K + lc4 * 4;
    const float* Bg = B + (size_t)(bn + lrow) * K + lc4 * 4;

    float4 ra[2], rb[2];

    float acc[4][4][4];
#pragma unroll
    for (int i = 0; i < 4; i++)
#pragma unroll
        for (int j = 0; j < 4; j++)
#pragma unroll
            for (int r = 0; r < 4; r++) acc[i][j][r] = 0.0f;

    const int NC = K / KC;

#pragma unroll
    for (int j = 0; j < 2; j++) {
        ra[j] = *(const float4*)(Ag + j * 4);
        rb[j] = *(const float4*)(Bg + j * 4);
    }
    {
        const int si = lrow * SA + lc4 * 4;
#pragma unroll
        for (int j = 0; j < 2; j++) {
            As[0][si + j * 4 + 0] = f2tf32(ra[j].x);
            As[0][si + j * 4 + 1] = f2tf32(ra[j].y);
            As[0][si + j * 4 + 2] = f2tf32(ra[j].z);
            As[0][si + j * 4 + 3] = f2tf32(ra[j].w);
            Bs[0][si + j * 4 + 0] = f2tf32(rb[j].x);
            Bs[0][si + j * 4 + 1] = f2tf32(rb[j].y);
            Bs[0][si + j * 4 + 2] = f2tf32(rb[j].z);
            Bs[0][si + j * 4 + 3] = f2tf32(rb[j].w);
        }
    }
    __syncthreads();

    for (int c = 0; c < NC; c++) {
        const int buf = c & 1;
        if (c + 1 < NC) {
            const size_t off = (size_t)(c + 1) * KC;
#pragma unroll
            for (int j = 0; j < 2; j++) {
                ra[j] = *(const float4*)(Ag + off + j * 4);
                rb[j] = *(const float4*)(Bg + off + j * 4);
            }
        }

#pragma unroll
        for (int ks = 0; ks < KC; ks += 8) {
            uint32_t af[4][4];
            uint32_t bf[4][2];
#pragma unroll
            for (int mt = 0; mt < 4; mt++) {
                const int r0 = (wm + mt * 16 + g) * SA + ks + t;
                af[mt][0] = As[buf][r0];
                af[mt][1] = As[buf][r0 + 8 * SA];
                af[mt][2] = As[buf][r0 + 4];
                af[mt][3] = As[buf][r0 + 8 * SA + 4];
            }
#pragma unroll
            for (int nt = 0; nt < 4; nt++) {
                const int r0 = (wn + nt * 8 + g) * SA + ks + t;
                bf[nt][0] = Bs[buf][r0];
                bf[nt][1] = Bs[buf][r0 + 4];
            }
#pragma unroll
            for (int mt = 0; mt < 4; mt++)
#pragma unroll
                for (int nt = 0; nt < 4; nt++)
                    MMA_TF32(acc[mt][nt], af[mt][0], af[mt][1], af[mt][2], af[mt][3],
                             bf[nt][0], bf[nt][1]);
        }

        if (c + 1 < NC) {
            const int nb = (c + 1) & 1;
            const int si = lrow * SA + lc4 * 4;
#pragma unroll
            for (int j = 0; j < 2; j++) {
                As[nb][si + j * 4 + 0] = f2tf32(ra[j].x);
                As[nb][si + j * 4 + 1] = f2tf32(ra[j].y);
                As[nb][si + j * 4 + 2] = f2tf32(ra[j].z);
                As[nb][si + j * 4 + 3] = f2tf32(ra[j].w);
                Bs[nb][si + j * 4 + 0] = f2tf32(rb[j].x);
                Bs[nb][si + j * 4 + 1] = f2tf32(rb[j].y);
                Bs[nb][si + j * 4 + 2] = f2tf32(rb[j].z);
                Bs[nb][si + j * 4 + 3] = f2tf32(rb[j].w);
            }
            __syncthreads();
        }
    }

#pragma unroll
    for (int mt = 0; mt < 4; mt++) {
#pragma unroll
        for (int nt = 0; nt < 4; nt++) {
            const int row = bm + wm + mt * 16 + g;
            const int col = bn + wn + nt * 8 + t * 2;
            float2 v0 = make_float2(acc[mt][nt][0] * scale, acc[mt][nt][1] * scale);
            float2 v1 = make_float2(acc[mt][nt][2] * scale, acc[mt][nt][3] * scale);
            if (bias) {
                float2 bv = *(const float2*)&bias[col];
                v0.x += bv.x; v0.y += bv.y;
                v1.x += bv.x; v1.y += bv.y;
            }
            *(float2*)&C[(size_t)row * N + col] = v0;
            *(float2*)&C[(size_t)(row + 8) * N + col] = v1;
        }
    }
}

// ===========================================================================
// Flash attention with tf32 mma.sync.
// Block: 128 queries x one (b,h). 8 warps; warp w owns query rows [16w,16w+16).
// Loop over 16 key-tiles of 64. d = 64. Scale pre-folded into Q.
// smem stride 68: fragment loads hit banks 4g+t -> conflict-free.
// ===========================================================================
#define AST 68
#define ATT2_SMEM ((128 + 64 + 64 + 128) * AST * 4)

__global__ __launch_bounds__(256) void attn_mma(
    const float* __restrict__ Q, const float* __restrict__ K,
    const float* __restrict__ V, float* __restrict__ O)
{
    extern __shared__ uint32_t sm2[];
    uint32_t* sQ  = sm2;                 // [128][AST]  (q rows, d cols)
    uint32_t* sK  = sQ + 128 * AST;      // [64][AST]   (key rows, d cols)
    uint32_t* sVt = sK + 64 * AST;       // [64][AST]   (d rows, key cols)
    uint32_t* sP  = sVt + 64 * AST;      // [128][AST]  (q rows, key cols)

    const int b = blockIdx.z;
    const int h = blockIdx.y;
    const int qt = blockIdx.x;

    const int tid = threadIdx.x;
    const int wid = tid >> 5;
    const int lane = tid & 31;
    const int g = lane >> 2;
    const int t = lane & 3;

    // ---- load Q tile (128 x 64), already scaled by 1/8 at projection ----
    {
        const int row = tid >> 1;
        const int half = tid & 1;
        const float* qg = Q + (size_t)(b * SQ_TOT + qt * 128 + row) * DMODEL
                            + h * DHEAD + half * 32;
        uint32_t* dst = sQ + row * AST + half * 32;
#pragma unroll
        for (int i = 0; i < 8; i++) {
            float4 v = *(const float4*)(qg + i * 4);
            dst[i * 4 + 0] = f2tf32(v.x);
            dst[i * 4 + 1] = f2tf32(v.y);
            dst[i * 4 + 2] = f2tf32(v.z);
            dst[i * 4 + 3] = f2tf32(v.w);
        }
    }

    float m0 = -1e30f, m1 = -1e30f, l0 = 0.0f, l1 = 0.0f;
    float o[8][4];
#pragma unroll
    for (int dt = 0; dt < 8; dt++)
#pragma unroll
        for (int r = 0; r < 4; r++) o[dt][r] = 0.0f;

    const int krow = tid >> 2;      // 0..63
    const int q4 = tid & 3;

    for (int kt = 0; kt < SK_TOT / 64; kt++) {
        __syncthreads();   // prev iteration done with sK/sVt (and Q visible on iter 0)

        // ---- load K tile [key][d] and V^T tile [d][key] ----
        {
            const size_t base = (size_t)(b * SK_TOT + kt * 64 + krow) * DMODEL + h * DHEAD;
            const float* kg = K + base;
            const float* vg = V + base;
#pragma unroll
            for (int i = 0; i < 4; i++) {
                const int col0 = (q4 + i * 4) * 4;
                float4 kv = *(const float4*)(kg + col0);
                uint32_t* kd = sK + krow * AST + col0;
                kd[0] = f2tf32(kv.x); kd[1] = f2tf32(kv.y);
                kd[2] = f2tf32(kv.z); kd[3] = f2tf32(kv.w);
                float4 vv = *(const float4*)(vg + col0);
                sVt[(col0 + 0) * AST + krow] = f2tf32(vv.x);
                sVt[(col0 + 1) * AST + krow] = f2tf32(vv.y);
                sVt[(col0 + 2) * AST + krow] = f2tf32(vv.z);
                sVt[(col0 + 3) * AST + krow] = f2tf32(vv.w);
            }
        }
        __syncthreads();

        // ---- S = Q @ K^T (16 rows x 64 keys per warp) ----
        float s[8][4];
#pragma unroll
        for (int nt = 0; nt < 8; nt++)
#pragma unroll
            for (int r = 0; r < 4; r++) s[nt][r] = 0.0f;

        const int qr0 = (wid * 16 + g) * AST;
#pragma unroll
        for (int ks = 0; ks < 8; ks++) {
            const int kc = ks * 8 + t;
            uint32_t a0 = sQ[qr0 + kc];
            uint32_t a1 = sQ[qr0 + 8 * AST + kc];
            uint32_t a2 = sQ[qr0 + kc + 4];
            uint32_t a3 = sQ[qr0 + 8 * AST + kc + 4];
#pragma unroll
            for (int nt = 0; nt < 8; nt++) {
                uint32_t b0 = sK[(nt * 8 + g) * AST + kc];
                uint32_t b1 = sK[(nt * 8 + g) * AST + kc + 4];
                MMA_TF32(s[nt], a0, a1, a2, a3, b0, b1);
            }
        }

        // ---- online softmax (rows g and g+8 of this warp's 16-row block) ----
        float ml0 = -1e30f, ml1 = -1e30f;
#pragma unroll
        for (int nt = 0; nt < 8; nt++) {
            ml0 = fmaxf(ml0, fmaxf(s[nt][0], s[nt][1]));
            ml1 = fmaxf(ml1, fmaxf(s[nt][2], s[nt][3]));
        }
        ml0 = fmaxf(ml0, __shfl_xor_sync(0xffffffffu, ml0, 1));
        ml0 = fmaxf(ml0, __shfl_xor_sync(0xffffffffu, ml0, 2));
        ml1 = fmaxf(ml1, __shfl_xor_sync(0xffffffffu, ml1, 1));
        ml1 = fmaxf(ml1, __shfl_xor_sync(0xffffffffu, ml1, 2));

        const float mn0 = fmaxf(m0, ml0);
        const float mn1 = fmaxf(m1, ml1);
        const float al0 = __expf(m0 - mn0);
        const float al1 = __expf(m1 - mn1);
        m0 = mn0; m1 = mn1;

        float rs0 = 0.0f, rs1 = 0.0f;
        uint32_t* pr0 = sP + (wid * 16 + g) * AST + 2 * t;
        uint32_t* pr1 = pr0 + 8 * AST;
#pragma unroll
        for (int nt = 0; nt < 8; nt++) {
            float p00 = __expf(s[nt][0] - mn0);
            float p01 = __expf(s[nt][1] - mn0);
            float p10 = __expf(s[nt][2] - mn1);
            float p11 = __expf(s[nt][3] - mn1);
            rs0 += p00 + p01;
            rs1 += p10 + p11;
            uint32_t u0 = f2tf32(p00), u1 = f2tf32(p01);
            uint32_t u2 = f2tf32(p10), u3 = f2tf32(p11);
            asm volatile("st.shared.v2.b32 [%0], {%1,%2};"
                         :: "l"(__cvta_generic_to_shared(pr0 + nt * 8)), "r"(u0), "r"(u1) : "memory");
            asm volatile("st.shared.v2.b32 [%0], {%1,%2};"
                         :: "l"(__cvta_generic_to_shared(pr1 + nt * 8)), "r"(u2), "r"(u3) : "memory");
        }
        rs0 += __shfl_xor_sync(0xffffffffu, rs0, 1);
        rs0 += __shfl_xor_sync(0xffffffffu, rs0, 2);
        rs1 += __shfl_xor_sync(0xffffffffu, rs1, 1);
        rs1 += __shfl_xor_sync(0xffffffffu, rs1, 2);
        l0 = l0 * al0 + rs0;
        l1 = l1 * al1 + rs1;
#pragma unroll
        for (int dt = 0; dt < 8; dt++) {
            o[dt][0] *= al0; o[dt][1] *= al0;
            o[dt][2] *= al1; o[dt][3] *= al1;
        }
        __syncwarp();   // sP rows of this warp written by this warp only

        // ---- O += P @ V (16 rows x 64 d per warp) ----
        const int pr = (wid * 16 + g) * AST;
#pragma unroll
        for (int ks = 0; ks < 8; ks++) {
            const int kc = ks * 8 + t;
            uint32_t a0 = sP[pr + kc];
            uint32_t a1 = sP[pr + 8 * AST + kc];
            uint32_t a2 = sP[pr + kc + 4];
            uint32_t a3 = sP[pr + 8 * AST + kc + 4];
#pragma unroll
            for (int dt = 0; dt < 8; dt++) {
                uint32_t b0 = sVt[(dt * 8 + g) * AST + kc];
                uint32_t b1 = sVt[(dt * 8 + g) * AST + kc + 4];
                MMA_TF32(o[dt], a0, a1, a2, a3, b0, b1);
            }
        }
    }

    // ---- epilogue ----
    const float inv0 = 1.0f / l0;
    const float inv1 = 1.0f / l1;
    const size_t row0 = (size_t)(b * SQ_TOT + qt * 128 + wid * 16 + g);
    float* o0 = O + row0 * DMODEL + h * DHEAD + 2 * t;
    float* o1 = o0 + 8 * DMODEL;
#pragma unroll
    for (int dt = 0; dt < 8; dt++) {
        *(float2*)(o0 + dt * 8) = make_float2(o[dt][0] * inv0, o[dt][1] * inv0);
        *(float2*)(o1 + dt * 8) = make_float2(o[dt][2] * inv1, o[dt][3] * inv1);
    }
}

// ===========================================================================
extern "C" void kernel_launch(void* const* d_in, const int* in_sizes, int n_in,
                              void* d_out, int out_size)
{
    const float* x   = (const float*)d_in[0];
    const float* ctx = (const float*)d_in[1];
    const float* Wq  = (const float*)d_in[2];
    const float* Wk  = (const float*)d_in[3];
    const float* Wv  = (const float*)d_in[4];
    const float* Wo  = (const float*)d_in[5];
    const float* bo  = (const float*)d_in[6];
    float* out = (float*)d_out;

    float *qb, *kb, *vb, *ab;
    cudaGetSymbolAddress((void**)&qb, g_Q);
    cudaGetSymbolAddress((void**)&kb, g_K);
    cudaGetSymbolAddress((void**)&vb, g_V);
    cudaGetSymbolAddress((void**)&ab, g_A);

    cudaFuncSetAttribute(attn_mma,
                         cudaFuncAttributeMaxDynamicSharedMemorySize, ATT2_SMEM);

    const int M_Q = BATCH * SQ_TOT;   // 12288
    const int M_KV = BATCH * SK_TOT;  // 2048

    gemm_mma<<<dim3(DMODEL / 128, M_Q / 128), 256>>>(
        x, Wq, qb, M_Q, DMODEL, DMODEL, nullptr, 0.125f);  // fold softmax scale
    gemm_mma<<<dim3(DMODEL / 128, M_KV / 128), 256>>>(
        ctx, Wk, kb, M_KV, DMODEL, DMODEL, nullptr, 1.0f);
    gemm_mma<<<dim3(DMODEL / 128, M_KV / 128), 256>>>(
        ctx, Wv, vb, M_KV, DMODEL, DMODEL, nullptr, 1.0f);

    attn_mma<<<dim3(SQ_TOT / 128, NHEADS, BATCH), 256, ATT2_SMEM>>>(qb, kb, vb, ab);

    gemm_mma<<<dim3(DMODEL / 128, M_Q / 128), 256>>>(
        ab, Wo, out, M_Q, DMODEL, DMODEL, bo, 1.0f);
}

// round 5
// speedup vs baseline: 3.0260x; 1.0605x over previous
#include <cuda_runtime.h>
#include <cstdint>
#include <math.h>

// Problem constants
#define DMODEL 1024
#define NHEADS 16
#define DHEAD  64
#define SQ_TOT 6144   // per batch
#define SK_TOT 1024
#define BATCH  2

// Scratch (allocation-free rule: __device__ globals). All tf32-bit uint32.
__device__ uint32_t g_xT[BATCH * SQ_TOT * DMODEL];
__device__ uint32_t g_cT[BATCH * SK_TOT * DMODEL];
__device__ uint32_t g_wqT[DMODEL * DMODEL];
__device__ uint32_t g_wkT[DMODEL * DMODEL];
__device__ uint32_t g_wvT[DMODEL * DMODEL];
__device__ uint32_t g_woT[DMODEL * DMODEL];
__device__ uint32_t g_Qt[BATCH * SQ_TOT * DMODEL];   // scaled by 0.125
__device__ uint32_t g_Kt[BATCH * SK_TOT * DMODEL];
__device__ uint32_t g_Vt[BATCH * NHEADS * DHEAD * SK_TOT]; // [b][h][d][key]
__device__ uint32_t g_At[BATCH * SQ_TOT * DMODEL];

__device__ __forceinline__ uint32_t f2tf32(float x) {
    uint32_t u;
    asm("cvt.rna.tf32.f32 %0, %1;" : "=r"(u) : "f"(x));
    return u;
}

__device__ __forceinline__ uint32_t smem_u32(const void* p) {
    uint32_t a;
    asm("{ .reg .u64 t; cvta.to.shared.u64 t, %1; cvt.u32.u64 %0, t; }"
        : "=r"(a) : "l"(p));
    return a;
}

#define CP16(dst, src) \
    asm volatile("cp.async.cg.shared.global [%0], [%1], 16;" :: "r"(dst), "l"(src))
#define CP_COMMIT() asm volatile("cp.async.commit_group;" ::: "memory")
#define CP_WAIT(n)  asm volatile("cp.async.wait_group %0;" :: "n"(n) : "memory")

#define MMA_TF32(d, a0, a1, a2, a3, b0, b1) \
    asm volatile( \
        "mma.sync.aligned.m16n8k8.row.col.f32.tf32.tf32.f32 " \
        "{%0,%1,%2,%3}, {%4,%5,%6,%7}, {%8,%9}, {%0,%1,%2,%3};" \
        : "+f"((d)[0]), "+f"((d)[1]), "+f"((d)[2]), "+f"((d)[3]) \
        : "r"(a0), "r"(a1), "r"(a2), "r"(a3), "r"(b0), "r"(b1))

// ===========================================================================
// fp32 -> tf32 bit conversion (grid-stride float4)
// ===========================================================================
__global__ void cvt_tf32(const float* __restrict__ in, uint32_t* __restrict__ out, int n)
{
    int i = (blockIdx.x * blockDim.x + threadIdx.x) * 4;
    if (i < n) {
        float4 v = *(const float4*)(in + i);
        uint4 u;
        u.x = f2tf32(v.x); u.y = f2tf32(v.y);
        u.z = f2tf32(v.z); u.w = f2tf32(v.w);
        *(uint4*)(out + i) = u;
    }
}

// ===========================================================================
// tf32 mma GEMM NT, pre-converted operands, 3-stage cp.async pipeline.
// CTA 128x128, 256 threads = 8 warps (2 M x 4 N), warp tile 64x32, KC=16.
// Epilogue modes: 0 = fp32 out + bias; 1 = tf32 out, scaled; 2 = tf32 out,
// transposed to [b][h][d][key] (V layout for attention).
// ===========================================================================
#define KC 16
#define SA 20
#define NST 3
#define GP_SMEM (2 * NST * 128 * SA * 4)

__global__ __launch_bounds__(256) void gemm_tf32p(
    const uint32_t* __restrict__ A, const uint32_t* __restrict__ B,
    float* __restrict__ Cf, uint32_t* __restrict__ Ct,
    int M, int N, int K, const float* __restrict__ bias, float scale, int mode)
{
    extern __shared__ uint32_t dyn[];
    uint32_t* As = dyn;                      // [NST][128*SA]
    uint32_t* Bs = dyn + NST * 128 * SA;

    const int tid = threadIdx.x;
    const int wid = tid >> 5;
    const int lane = tid & 31;
    const int g = lane >> 2;
    const int t = lane & 3;
    const int wm = (wid & 1) * 64;
    const int wn = (wid >> 1) * 32;
    const int bm = blockIdx.y * 128;
    const int bn = blockIdx.x * 128;

    // cp.async mapping: row tid>>1, 32B half (tid&1)
    const int lrow = tid >> 1;
    const int lh = tid & 1;
    const uint32_t* Ag = A + (size_t)(bm + lrow) * K + lh * 8;
    const uint32_t* Bg = B + (size_t)(bn + lrow) * K + lh * 8;
    const uint32_t sAbase = smem_u32(As) + (lrow * SA + lh * 8) * 4;
    const uint32_t sBbase = smem_u32(Bs) + (lrow * SA + lh * 8) * 4;
    const uint32_t stageB = 128 * SA * 4;

    float acc[4][4][4];
#pragma unroll
    for (int i = 0; i < 4; i++)
#pragma unroll
        for (int j = 0; j < 4; j++)
#pragma unroll
            for (int r = 0; r < 4; r++) acc[i][j][r] = 0.0f;

    const int NC = K / KC;

    // prologue: issue chunks 0..NST-2
#pragma unroll
    for (int c = 0; c < NST - 1; c++) {
        CP16(sAbase + c * stageB,      Ag + (size_t)c * KC);
        CP16(sAbase + c * stageB + 16, Ag + (size_t)c * KC + 4);
        CP16(sBbase + c * stageB,      Bg + (size_t)c * KC);
        CP16(sBbase + c * stageB + 16, Bg + (size_t)c * KC + 4);
        CP_COMMIT();
    }

    for (int c = 0; c < NC; c++) {
        const int st = c % NST;
        CP_WAIT(NST - 2);
        __syncthreads();

        // issue chunk c+NST-1
        {
            const int cn = c + NST - 1;
            if (cn < NC) {
                const int sn = cn % NST;
                CP16(sAbase + sn * stageB,      Ag + (size_t)cn * KC);
                CP16(sAbase + sn * stageB + 16, Ag + (size_t)cn * KC + 4);
                CP16(sBbase + sn * stageB,      Bg + (size_t)cn * KC);
                CP16(sBbase + sn * stageB + 16, Bg + (size_t)cn * KC + 4);
            }
            CP_COMMIT();
        }

        const uint32_t* Ast = As + st * 128 * SA;
        const uint32_t* Bst = Bs + st * 128 * SA;
#pragma unroll
        for (int ks = 0; ks < KC; ks += 8) {
            uint32_t af[4][4];
            uint32_t bf[4][2];
#pragma unroll
            for (int mt = 0; mt < 4; mt++) {
                const int r0 = (wm + mt * 16 + g) * SA + ks + t;
                af[mt][0] = Ast[r0];
                af[mt][1] = Ast[r0 + 8 * SA];
                af[mt][2] = Ast[r0 + 4];
                af[mt][3] = Ast[r0 + 8 * SA + 4];
            }
#pragma unroll
            for (int nt = 0; nt < 4; nt++) {
                const int r0 = (wn + nt * 8 + g) * SA + ks + t;
                bf[nt][0] = Bst[r0];
                bf[nt][1] = Bst[r0 + 4];
            }
#pragma unroll
            for (int mt = 0; mt < 4; mt++)
#pragma unroll
                for (int nt = 0; nt < 4; nt++)
                    MMA_TF32(acc[mt][nt], af[mt][0], af[mt][1], af[mt][2], af[mt][3],
                             bf[nt][0], bf[nt][1]);
        }
        __syncthreads();
    }

    // Epilogue
#pragma unroll
    for (int mt = 0; mt < 4; mt++) {
#pragma unroll
        for (int nt = 0; nt < 4; nt++) {
            const int row = bm + wm + mt * 16 + g;
            const int col = bn + wn + nt * 8 + t * 2;
            if (mode == 0) {
                float2 bv = *(const float2*)&bias[col];
                float2 v0 = make_float2(acc[mt][nt][0] + bv.x, acc[mt][nt][1] + bv.y);
                float2 v1 = make_float2(acc[mt][nt][2] + bv.x, acc[mt][nt][3] + bv.y);
                *(float2*)&Cf[(size_t)row * N + col] = v0;
                *(float2*)&Cf[(size_t)(row + 8) * N + col] = v1;
            } else if (mode == 1) {
                uint2 u0 = make_uint2(f2tf32(acc[mt][nt][0] * scale),
                                      f2tf32(acc[mt][nt][1] * scale));
                uint2 u1 = make_uint2(f2tf32(acc[mt][nt][2] * scale),
                                      f2tf32(acc[mt][nt][3] * scale));
                *(uint2*)&Ct[(size_t)row * N + col] = u0;
                *(uint2*)&Ct[(size_t)(row + 8) * N + col] = u1;
            } else {
                // V transpose: row = b*1024+key, col = h*64+d -> [b][h][d][key]
                const int b = row >> 10, key = row & 1023;
                const int h = col >> 6, d = col & 63;
                const size_t base = ((size_t)(b * NHEADS + h) * DHEAD + d) * SK_TOT + key;
                Ct[base]                = f2tf32(acc[mt][nt][0]);
                Ct[base + SK_TOT]       = f2tf32(acc[mt][nt][1]);
                Ct[base + 8]            = f2tf32(acc[mt][nt][2]);
                Ct[base + SK_TOT + 8]   = f2tf32(acc[mt][nt][3]);
            }
        }
    }
}

// ===========================================================================
// Flash attention, tf32 mma, pre-converted tf32 inputs, cp.async loads.
// Block: 128 queries x one (b,h). 8 warps; warp w owns rows [16w,16w+16).
// ===========================================================================
#define AST 68
#define ATT_SMEM ((128 + 64 + 64 + 128) * AST * 4)

__global__ __launch_bounds__(256) void attn_mma(
    const uint32_t* __restrict__ Q, const uint32_t* __restrict__ K,
    const uint32_t* __restrict__ V, uint32_t* __restrict__ O)
{
    extern __shared__ uint32_t sm2[];
    uint32_t* sQ  = sm2;                 // [128][AST]
    uint32_t* sK  = sQ + 128 * AST;      // [64][AST]  (key rows, d cols)
    uint32_t* sVt = sK + 64 * AST;       // [64][AST]  (d rows, key cols)
    uint32_t* sP  = sVt + 64 * AST;      // [128][AST]

    const int b = blockIdx.z;
    const int h = blockIdx.y;
    const int qt = blockIdx.x;

    const int tid = threadIdx.x;
    const int wid = tid >> 5;
    const int lane = tid & 31;
    const int g = lane >> 2;
    const int t = lane & 3;

    const uint32_t sQa  = smem_u32(sQ);
    const uint32_t sKa  = smem_u32(sK);
    const uint32_t sVta = smem_u32(sVt);

    // ---- Q tile (128x64) cp.async: row tid>>1, 32-col half tid&1 ----
    {
        const int row = tid >> 1, half = tid & 1;
        const uint32_t* qg = Q + (size_t)(b * SQ_TOT + qt * 128 + row) * DMODEL
                               + h * DHEAD + half * 32;
        const uint32_t qd = sQa + (row * AST + half * 32) * 4;
#pragma unroll
        for (int i = 0; i < 8; i++) CP16(qd + i * 16, qg + i * 4);
    }

    float m0 = -1e30f, m1 = -1e30f, l0 = 0.0f, l1 = 0.0f;
    float o[8][4];
#pragma unroll
    for (int dt = 0; dt < 8; dt++)
#pragma unroll
        for (int r = 0; r < 4; r++) o[dt][r] = 0.0f;

    const int lrow = tid >> 2;       // 0..63
    const int lq = (tid & 3) * 16;   // 16-col chunk

    for (int kt = 0; kt < SK_TOT / 64; kt++) {
        __syncthreads();   // all warps done with sK/sVt of prev iter

        // ---- K tile [key][d] and Vt tile [d][key], straight copies ----
        {
            const uint32_t* kg = K + (size_t)(b * SK_TOT + kt * 64 + lrow) * DMODEL
                                   + h * DHEAD + lq;
            const uint32_t* vg = V + ((size_t)(b * NHEADS + h) * DHEAD + lrow) * SK_TOT
                                   + kt * 64 + lq;
            const uint32_t kd = sKa + (lrow * AST + lq) * 4;
            const uint32_t vd = sVta + (lrow * AST + lq) * 4;
#pragma unroll
            for (int i = 0; i < 4; i++) {
                CP16(kd + i * 16, kg + i * 4);
                CP16(vd + i * 16, vg + i * 4);
            }
        }
        CP_COMMIT();
        CP_WAIT(0);
        __syncthreads();

        // ---- S = Q @ K^T ----
        float s[8][4];
#pragma unroll
        for (int nt = 0; nt < 8; nt++)
#pragma unroll
            for (int r = 0; r < 4; r++) s[nt][r] = 0.0f;

        const int qr0 = (wid * 16 + g) * AST;
#pragma unroll
        for (int ks = 0; ks < 8; ks++) {
            const int kc = ks * 8 + t;
            uint32_t a0 = sQ[qr0 + kc];
            uint32_t a1 = sQ[qr0 + 8 * AST + kc];
            uint32_t a2 = sQ[qr0 + kc + 4];
            uint32_t a3 = sQ[qr0 + 8 * AST + kc + 4];
#pragma unroll
            for (int nt = 0; nt < 8; nt++) {
                uint32_t b0 = sK[(nt * 8 + g) * AST + kc];
                uint32_t b1 = sK[(nt * 8 + g) * AST + kc + 4];
                MMA_TF32(s[nt], a0, a1, a2, a3, b0, b1);
            }
        }

        // ---- online softmax ----
        float ml0 = -1e30f, ml1 = -1e30f;
#pragma unroll
        for (int nt = 0; nt < 8; nt++) {
            ml0 = fmaxf(ml0, fmaxf(s[nt][0], s[nt][1]));
            ml1 = fmaxf(ml1, fmaxf(s[nt][2], s[nt][3]));
        }
        ml0 = fmaxf(ml0, __shfl_xor_sync(0xffffffffu, ml0, 1));
        ml0 = fmaxf(ml0, __shfl_xor_sync(0xffffffffu, ml0, 2));
        ml1 = fmaxf(ml1, __shfl_xor_sync(0xffffffffu, ml1, 1));
        ml1 = fmaxf(ml1, __shfl_xor_sync(0xffffffffu, ml1, 2));

        const float mn0 = fmaxf(m0, ml0);
        const float mn1 = fmaxf(m1, ml1);
        const float al0 = __expf(m0 - mn0);
        const float al1 = __expf(m1 - mn1);
        m0 = mn0; m1 = mn1;

        float rs0 = 0.0f, rs1 = 0.0f;
        uint32_t* pr0 = sP + (wid * 16 + g) * AST + 2 * t;
        uint32_t* pr1 = pr0 + 8 * AST;
#pragma unroll
        for (int nt = 0; nt < 8; nt++) {
            float p00 = __expf(s[nt][0] - mn0);
            float p01 = __expf(s[nt][1] - mn0);
            float p10 = __expf(s[nt][2] - mn1);
            float p11 = __expf(s[nt][3] - mn1);
            rs0 += p00 + p01;
            rs1 += p10 + p11;
            uint32_t u0 = f2tf32(p00), u1 = f2tf32(p01);
            uint32_t u2 = f2tf32(p10), u3 = f2tf32(p11);
            asm volatile("st.shared.v2.b32 [%0], {%1,%2};"
                         :: "l"(__cvta_generic_to_shared(pr0 + nt * 8)), "r"(u0), "r"(u1) : "memory");
            asm volatile("st.shared.v2.b32 [%0], {%1,%2};"
                         :: "l"(__cvta_generic_to_shared(pr1 + nt * 8)), "r"(u2), "r"(u3) : "memory");
        }
        rs0 += __shfl_xor_sync(0xffffffffu, rs0, 1);
        rs0 += __shfl_xor_sync(0xffffffffu, rs0, 2);
        rs1 += __shfl_xor_sync(0xffffffffu, rs1, 1);
        rs1 += __shfl_xor_sync(0xffffffffu, rs1, 2);
        l0 = l0 * al0 + rs0;
        l1 = l1 * al1 + rs1;
#pragma unroll
        for (int dt = 0; dt < 8; dt++) {
            o[dt][0] *= al0; o[dt][1] *= al0;
            o[dt][2] *= al1; o[dt][3] *= al1;
        }
        __syncwarp();   // this warp's sP rows written by this warp only

        // ---- O += P @ V ----
        const int pr = (wid * 16 + g) * AST;
#pragma unroll
        for (int ks = 0; ks < 8; ks++) {
            const int kc = ks * 8 + t;
            uint32_t a0 = sP[pr + kc];
            uint32_t a1 = sP[pr + 8 * AST + kc];
            uint32_t a2 = sP[pr + kc + 4];
            uint32_t a3 = sP[pr + 8 * AST + kc + 4];
#pragma unroll
            for (int dt = 0; dt < 8; dt++) {
                uint32_t b0 = sVt[(dt * 8 + g) * AST + kc];
                uint32_t b1 = sVt[(dt * 8 + g) * AST + kc + 4];
                MMA_TF32(o[dt], a0, a1, a2, a3, b0, b1);
            }
        }
    }

    // ---- epilogue: write tf32 into g_At ----
    const float inv0 = 1.0f / l0;
    const float inv1 = 1.0f / l1;
    const size_t row0 = (size_t)(b * SQ_TOT + qt * 128 + wid * 16 + g);
    uint32_t* o0 = O + row0 * DMODEL + h * DHEAD + 2 * t;
    uint32_t* o1 = o0 + 8 * DMODEL;
#pragma unroll
    for (int dt = 0; dt < 8; dt++) {
        *(uint2*)(o0 + dt * 8) = make_uint2(f2tf32(o[dt][0] * inv0), f2tf32(o[dt][1] * inv0));
        *(uint2*)(o1 + dt * 8) = make_uint2(f2tf32(o[dt][2] * inv1), f2tf32(o[dt][3] * inv1));
    }
}

// ===========================================================================
extern "C" void kernel_launch(void* const* d_in, const int* in_sizes, int n_in,
                              void* d_out, int out_size)
{
    const float* x   = (const float*)d_in[0];
    const float* ctx = (const float*)d_in[1];
    const float* Wq  = (const float*)d_in[2];
    const float* Wk  = (const float*)d_in[3];
    const float* Wv  = (const float*)d_in[4];
    const float* Wo  = (const float*)d_in[5];
    const float* bo  = (const float*)d_in[6];
    float* out = (float*)d_out;

    uint32_t *xT, *cT, *wqT, *wkT, *wvT, *woT, *qt, *kt, *vt, *at;
    cudaGetSymbolAddress((void**)&xT,  g_xT);
    cudaGetSymbolAddress((void**)&cT,  g_cT);
    cudaGetSymbolAddress((void**)&wqT, g_wqT);
    cudaGetSymbolAddress((void**)&wkT, g_wkT);
    cudaGetSymbolAddress((void**)&wvT, g_wvT);
    cudaGetSymbolAddress((void**)&woT, g_woT);
    cudaGetSymbolAddress((void**)&qt,  g_Qt);
    cudaGetSymbolAddress((void**)&kt,  g_Kt);
    cudaGetSymbolAddress((void**)&vt,  g_Vt);
    cudaGetSymbolAddress((void**)&at,  g_At);

    cudaFuncSetAttribute(gemm_tf32p,
                         cudaFuncAttributeMaxDynamicSharedMemorySize, GP_SMEM);
    cudaFuncSetAttribute(attn_mma,
                         cudaFuncAttributeMaxDynamicSharedMemorySize, ATT_SMEM);

    const int M_Q = BATCH * SQ_TOT;   // 12288
    const int M_KV = BATCH * SK_TOT;  // 2048
    const int NW = DMODEL * DMODEL;   // 1048576

    // Pre-convert inputs + weights to tf32 bits
    cvt_tf32<<<(M_Q * DMODEL / 4 + 255) / 256, 256>>>(x, xT, M_Q * DMODEL);
    cvt_tf32<<<(M_KV * DMODEL / 4 + 255) / 256, 256>>>(ctx, cT, M_KV * DMODEL);
    cvt_tf32<<<(NW / 4 + 255) / 256, 256>>>(Wq, wqT, NW);
    cvt_tf32<<<(NW / 4 + 255) / 256, 256>>>(Wk, wkT, NW);
    cvt_tf32<<<(NW / 4 + 255) / 256, 256>>>(Wv, wvT, NW);
    cvt_tf32<<<(NW / 4 + 255) / 256, 256>>>(Wo, woT, NW);

    // Projections (Q scaled by 1/8; V written transposed per-head)
    gemm_tf32p<<<dim3(DMODEL / 128, M_Q / 128), 256, GP_SMEM>>>(
        xT, wqT, nullptr, qt, M_Q, DMODEL, DMODEL, nullptr, 0.125f, 1);
    gemm_tf32p<<<dim3(DMODEL / 128, M_KV / 128), 256, GP_SMEM>>>(
        cT, wkT, nullptr, kt, M_KV, DMODEL, DMODEL, nullptr, 1.0f, 1);
    gemm_tf32p<<<dim3(DMODEL / 128, M_KV / 128), 256, GP_SMEM>>>(
        cT, wvT, nullptr, vt, M_KV, DMODEL, DMODEL, nullptr, 1.0f, 2);

    attn_mma<<<dim3(SQ_TOT / 128, NHEADS, BATCH), 256, ATT_SMEM>>>(qt, kt, vt, at);

    // Output projection + bias -> fp32 d_out
    gemm_tf32p<<<dim3(DMODEL / 128, M_Q / 128), 256, GP_SMEM>>>(
        at, woT, out, nullptr, M_Q, DMODEL, DMODEL, bo, 1.0f, 0);
}

// round 6
// speedup vs baseline: 4.0351x; 1.3335x over previous
#include <cuda_runtime.h>
#include <cuda_fp16.h>
#include <cstdint>

// Problem constants
#define DMODEL 1024
#define NHEADS 16
#define DHEAD  64
#define SQ_TOT 6144   // per batch
#define SK_TOT 1024
#define BATCH  2

// Scratch (allocation-free rule: __device__ globals), all fp16.
__device__ __half g_xH[BATCH * SQ_TOT * DMODEL];
__device__ __half g_cH[BATCH * SK_TOT * DMODEL];
__device__ __half g_wqH[DMODEL * DMODEL];
__device__ __half g_wkH[DMODEL * DMODEL];
__device__ __half g_wvH[DMODEL * DMODEL];
__device__ __half g_woH[DMODEL * DMODEL];
__device__ __half g_Qh[BATCH * SQ_TOT * DMODEL];   // pre-scaled by 0.125
__device__ __half g_Kh[BATCH * SK_TOT * DMODEL];
__device__ __half g_Vh[BATCH * NHEADS * DHEAD * SK_TOT]; // [b][h][d][key]
__device__ __half g_Ah[BATCH * SQ_TOT * DMODEL];

__device__ __forceinline__ uint32_t smem_u32(const void* p) {
    uint32_t a;
    asm("{ .reg .u64 t; cvta.to.shared.u64 t, %1; cvt.u32.u64 %0, t; }"
        : "=r"(a) : "l"(p));
    return a;
}

#define CP16(dst, src) \
    asm volatile("cp.async.cg.shared.global [%0], [%1], 16;" :: "r"(dst), "l"(src))
#define CP_COMMIT() asm volatile("cp.async.commit_group;" ::: "memory")
#define CP_WAIT(n)  asm volatile("cp.async.wait_group %0;" :: "n"(n) : "memory")

#define LDSM_X4(r0, r1, r2, r3, addr) \
    asm volatile("ldmatrix.sync.aligned.m8n8.x4.shared.b16 {%0,%1,%2,%3}, [%4];" \
        : "=r"(r0), "=r"(r1), "=r"(r2), "=r"(r3) : "r"(addr))

#define MMA_F16(d, a0, a1, a2, a3, b0, b1) \
    asm volatile( \
        "mma.sync.aligned.m16n8k16.row.col.f32.f16.f16.f32 " \
        "{%0,%1,%2,%3}, {%4,%5,%6,%7}, {%8,%9}, {%0,%1,%2,%3};" \
        : "+f"((d)[0]), "+f"((d)[1]), "+f"((d)[2]), "+f"((d)[3]) \
        : "r"(a0), "r"(a1), "r"(a2), "r"(a3), "r"(b0), "r"(b1))

// ===========================================================================
// fp32 -> fp16 conversion, 8 elements/thread
// ===========================================================================
__global__ void cvt_f16(const float* __restrict__ in, __half* __restrict__ out, int n)
{
    int i = (blockIdx.x * blockDim.x + threadIdx.x) * 8;
    if (i < n) {
        float4 a = *(const float4*)(in + i);
        float4 b = *(const float4*)(in + i + 4);
        __half2* o = (__half2*)(out + i);
        o[0] = __floats2half2_rn(a.x, a.y);
        o[1] = __floats2half2_rn(a.z, a.w);
        o[2] = __floats2half2_rn(b.x, b.y);
        o[3] = __floats2half2_rn(b.z, b.w);
    }
}

// ===========================================================================
// fp16 mma GEMM NT: C[m,n] = scale*sum_k A[m,k]*B[n,k] (+bias)
// CTA 128x128, 8 warps (2M x 4N), warp 64x32. KC=32 halves, 3-stage cp.async.
// smem row stride 40 halves (80B = 5x16B, odd -> ldmatrix conflict-free).
// Modes: 0 = fp32 out + bias; 1 = fp16 out scaled; 2 = fp16 out transposed
// to [b][h][d][key].
// ===========================================================================
#define KCH 32
#define SAH 40
#define NST 3
#define GSTAGE (128 * SAH)
#define GP_SMEM (2 * NST * GSTAGE * 2)

__global__ __launch_bounds__(256) void gemm_f16(
    const __half* __restrict__ A, const __half* __restrict__ B,
    float* __restrict__ Cf, __half* __restrict__ Ch,
    int M, int N, int K, const float* __restrict__ bias, float scale, int mode)
{
    extern __shared__ __half sh[];
    __half* As = sh;
    __half* Bs = sh + NST * GSTAGE;

    const int tid = threadIdx.x;
    const int wid = tid >> 5;
    const int lane = tid & 31;
    const int g = lane >> 2;
    const int t = lane & 3;
    const int wm = (wid & 1) * 64;
    const int wn = (wid >> 1) * 32;
    const int bm = blockIdx.y * 128;
    const int bn = blockIdx.x * 128;

    // cp.async mapping: row tid>>1, two 16B chunks
    const int lrow = tid >> 1;
    const int lc = (tid & 1) * 2;
    const __half* Ag = A + (size_t)(bm + lrow) * K + lc * 8;
    const __half* Bg = B + (size_t)(bn + lrow) * K + lc * 8;
    const uint32_t sA0 = smem_u32(As) + (lrow * SAH + lc * 8) * 2;
    const uint32_t sB0 = smem_u32(Bs) + (lrow * SAH + lc * 8) * 2;
    const uint32_t stB = GSTAGE * 2;

    // ldmatrix per-lane bases
    const int arow = (lane & 7) + ((lane >> 3) & 1) * 8;  // + wm + mt*16
    const int acol = (lane >> 4) * 8;                     // + ks*16
    const int brow = (lane & 7) + (lane >> 4) * 8;        // + wn + p*16
    const int bcol = ((lane >> 3) & 1) * 8;               // + ks*16
    const uint32_t aBase = smem_u32(As) + ((wm + arow) * SAH + acol) * 2;
    const uint32_t bBase = smem_u32(Bs) + ((wn + brow) * SAH + bcol) * 2;

    float acc[4][4][4];
#pragma unroll
    for (int i = 0; i < 4; i++)
#pragma unroll
        for (int j = 0; j < 4; j++)
#pragma unroll
            for (int r = 0; r < 4; r++) acc[i][j][r] = 0.0f;

    const int NC = K / KCH;   // 32

#pragma unroll
    for (int c = 0; c < NST - 1; c++) {
        CP16(sA0 + c * stB,      Ag + (size_t)c * KCH);
        CP16(sA0 + c * stB + 16, Ag + (size_t)c * KCH + 8);
        CP16(sB0 + c * stB,      Bg + (size_t)c * KCH);
        CP16(sB0 + c * stB + 16, Bg + (size_t)c * KCH + 8);
        CP_COMMIT();
    }

    for (int c = 0; c < NC; c++) {
        const int st = c % NST;
        CP_WAIT(NST - 2);
        __syncthreads();

        {
            const int cn = c + NST - 1;
            if (cn < NC) {
                const int sn = cn % NST;
                CP16(sA0 + sn * stB,      Ag + (size_t)cn * KCH);
                CP16(sA0 + sn * stB + 16, Ag + (size_t)cn * KCH + 8);
                CP16(sB0 + sn * stB,      Bg + (size_t)cn * KCH);
                CP16(sB0 + sn * stB + 16, Bg + (size_t)cn * KCH + 8);
            }
            CP_COMMIT();
        }

        const uint32_t aSt = aBase + st * stB;
        const uint32_t bSt = bBase + st * stB;
#pragma unroll
        for (int ks = 0; ks < 2; ks++) {
            uint32_t a[4][4];
#pragma unroll
            for (int mt = 0; mt < 4; mt++)
                LDSM_X4(a[mt][0], a[mt][1], a[mt][2], a[mt][3],
                        aSt + (mt * 16 * SAH + ks * 16) * 2);
#pragma unroll
            for (int p = 0; p < 2; p++) {
                uint32_t b0, b1, b2, b3;
                LDSM_X4(b0, b1, b2, b3, bSt + (p * 16 * SAH + ks * 16) * 2);
#pragma unroll
                for (int mt = 0; mt < 4; mt++) {
                    MMA_F16(acc[mt][2 * p],     a[mt][0], a[mt][1], a[mt][2], a[mt][3], b0, b1);
                    MMA_F16(acc[mt][2 * p + 1], a[mt][0], a[mt][1], a[mt][2], a[mt][3], b2, b3);
                }
            }
        }
        __syncthreads();
    }

    // Epilogue: thread owns (g, 2t) / (g+8, 2t) per m16n8 tile
#pragma unroll
    for (int mt = 0; mt < 4; mt++) {
#pragma unroll
        for (int nt = 0; nt < 4; nt++) {
            const int row = bm + wm + mt * 16 + g;
            const int col = bn + wn + nt * 8 + 2 * t;
            float c0 = acc[mt][nt][0], c1 = acc[mt][nt][1];
            float c2 = acc[mt][nt][2], c3 = acc[mt][nt][3];
            if (mode == 0) {
                float2 bv = *(const float2*)&bias[col];
                *(float2*)&Cf[(size_t)row * N + col] = make_float2(c0 + bv.x, c1 + bv.y);
                *(float2*)&Cf[(size_t)(row + 8) * N + col] = make_float2(c2 + bv.x, c3 + bv.y);
            } else if (mode == 1) {
                *(__half2*)&Ch[(size_t)row * N + col] =
                    __floats2half2_rn(c0 * scale, c1 * scale);
                *(__half2*)&Ch[(size_t)(row + 8) * N + col] =
                    __floats2half2_rn(c2 * scale, c3 * scale);
            } else {
                // V transpose: row = b*1024+key, col = h*64+d -> [b][h][d][key]
                const int b = row >> 10, key = row & 1023;
                const int h = col >> 6, d = col & 63;
                __half* base = Ch + ((size_t)((b * NHEADS + h) * DHEAD + d)) * SK_TOT;
                base[key]                 = __float2half(c0);
                base[SK_TOT + key]        = __float2half(c1);
                base[key + 8]             = __float2half(c2);
                base[SK_TOT + key + 8]    = __float2half(c3);
            }
        }
    }
}

// ===========================================================================
// Flash attention, fp16 mma + ldmatrix.
// Block: 128 queries x one (b,h); 8 warps; warp w owns rows [16w,16w+16).
// smem row stride 72 halves (144B = 9x16B, odd -> ldmatrix conflict-free).
// ===========================================================================
#define AS 72
#define ATT_SMEM ((128 + 64 + 64 + 128) * AS * 2)

__global__ __launch_bounds__(256) void attn_f16(
    const __half* __restrict__ Q, const __half* __restrict__ K,
    const __half* __restrict__ V, __half* __restrict__ O)
{
    extern __shared__ __half sma[];
    __half* sQ  = sma;               // [128][AS]  q rows x d
    __half* sK  = sQ + 128 * AS;     // [64][AS]   key rows x d
    __half* sVt = sK + 64 * AS;      // [64][AS]   d rows x key
    __half* sP  = sVt + 64 * AS;     // [128][AS]  q rows x key

    const int b = blockIdx.z;
    const int h = blockIdx.y;
    const int qt = blockIdx.x;

    const int tid = threadIdx.x;
    const int wid = tid >> 5;
    const int lane = tid & 31;
    const int g = lane >> 2;
    const int t = lane & 3;

    const uint32_t sQa  = smem_u32(sQ);
    const uint32_t sKa  = smem_u32(sK);
    const uint32_t sVta = smem_u32(sVt);

    // Q tile (128x64h): row tid>>1, 4 chunks of 16B
    {
        const int row = tid >> 1, c0 = (tid & 1) * 4;
        const __half* qg = Q + (size_t)(b * SQ_TOT + qt * 128 + row) * DMODEL
                             + h * DHEAD + c0 * 8;
        const uint32_t qd = sQa + (row * AS + c0 * 8) * 2;
#pragma unroll
        for (int i = 0; i < 4; i++) CP16(qd + i * 16, qg + i * 8);
    }

    // ldmatrix per-lane bases
    const int arow = (lane & 7) + ((lane >> 3) & 1) * 8;
    const int acol = (lane >> 4) * 8;
    const int brow = (lane & 7) + (lane >> 4) * 8;
    const int bcol = ((lane >> 3) & 1) * 8;
    const uint32_t aQ = sQa + ((wid * 16 + arow) * AS + acol) * 2;
    const uint32_t aP = smem_u32(sP) + ((wid * 16 + arow) * AS + acol) * 2;
    const uint32_t bK = sKa + (brow * AS + bcol) * 2;
    const uint32_t bV = sVta + (brow * AS + bcol) * 2;

    float m0 = -1e30f, m1 = -1e30f, l0 = 0.0f, l1 = 0.0f;
    float o[8][4];
#pragma unroll
    for (int dt = 0; dt < 8; dt++)
#pragma unroll
        for (int r = 0; r < 4; r++) o[dt][r] = 0.0f;

    const int lrow = tid >> 2;       // 0..63
    const int lc = (tid & 3) * 2;    // 2 chunks of 16B

    for (int kt = 0; kt < SK_TOT / 64; kt++) {
        __syncthreads();

        // K tile [key][d], Vt tile [d][key]
        {
            const __half* kg = K + (size_t)(b * SK_TOT + kt * 64 + lrow) * DMODEL
                                 + h * DHEAD + lc * 8;
            const __half* vg = V + ((size_t)((b * NHEADS + h) * DHEAD + lrow)) * SK_TOT
                                 + kt * 64 + lc * 8;
            const uint32_t kd = sKa + (lrow * AS + lc * 8) * 2;
            const uint32_t vd = sVta + (lrow * AS + lc * 8) * 2;
            CP16(kd, kg);      CP16(kd + 16, kg + 8);
            CP16(vd, vg);      CP16(vd + 16, vg + 8);
        }
        CP_COMMIT();
        CP_WAIT(0);
        __syncthreads();

        // ---- S = Q @ K^T ----
        float s[8][4];
#pragma unroll
        for (int nt = 0; nt < 8; nt++)
#pragma unroll
            for (int r = 0; r < 4; r++) s[nt][r] = 0.0f;

#pragma unroll
        for (int ks = 0; ks < 4; ks++) {
            uint32_t a0, a1, a2, a3;
            LDSM_X4(a0, a1, a2, a3, aQ + ks * 32);
#pragma unroll
            for (int p = 0; p < 4; p++) {
                uint32_t b0, b1, b2, b3;
                LDSM_X4(b0, b1, b2, b3, bK + (p * 16 * AS + ks * 16) * 2);
                MMA_F16(s[2 * p],     a0, a1, a2, a3, b0, b1);
                MMA_F16(s[2 * p + 1], a0, a1, a2, a3, b2, b3);
            }
        }

        // ---- online softmax ----
        float ml0 = -1e30f, ml1 = -1e30f;
#pragma unroll
        for (int nt = 0; nt < 8; nt++) {
            ml0 = fmaxf(ml0, fmaxf(s[nt][0], s[nt][1]));
            ml1 = fmaxf(ml1, fmaxf(s[nt][2], s[nt][3]));
        }
        ml0 = fmaxf(ml0, __shfl_xor_sync(0xffffffffu, ml0, 1));
        ml0 = fmaxf(ml0, __shfl_xor_sync(0xffffffffu, ml0, 2));
        ml1 = fmaxf(ml1, __shfl_xor_sync(0xffffffffu, ml1, 1));
        ml1 = fmaxf(ml1, __shfl_xor_sync(0xffffffffu, ml1, 2));

        const float mn0 = fmaxf(m0, ml0);
        const float mn1 = fmaxf(m1, ml1);
        const float al0 = __expf(m0 - mn0);
        const float al1 = __expf(m1 - mn1);
        m0 = mn0; m1 = mn1;

        float rs0 = 0.0f, rs1 = 0.0f;
        __half2* pr0 = (__half2*)&sP[(wid * 16 + g) * AS + 2 * t];
        __half2* pr1 = (__half2*)&sP[(wid * 16 + 8 + g) * AS + 2 * t];
#pragma unroll
        for (int nt = 0; nt < 8; nt++) {
            float p00 = __expf(s[nt][0] - mn0);
            float p01 = __expf(s[nt][1] - mn0);
            float p10 = __expf(s[nt][2] - mn1);
            float p11 = __expf(s[nt][3] - mn1);
            rs0 += p00 + p01;
            rs1 += p10 + p11;
            pr0[nt * 4] = __floats2half2_rn(p00, p01);
            pr1[nt * 4] = __floats2half2_rn(p10, p11);
        }
        rs0 += __shfl_xor_sync(0xffffffffu, rs0, 1);
        rs0 += __shfl_xor_sync(0xffffffffu, rs0, 2);
        rs1 += __shfl_xor_sync(0xffffffffu, rs1, 1);
        rs1 += __shfl_xor_sync(0xffffffffu, rs1, 2);
        l0 = l0 * al0 + rs0;
        l1 = l1 * al1 + rs1;
#pragma unroll
        for (int dt = 0; dt < 8; dt++) {
            o[dt][0] *= al0; o[dt][1] *= al0;
            o[dt][2] *= al1; o[dt][3] *= al1;
        }
        __syncwarp();   // this warp's sP rows fully written

        // ---- O += P @ V ----
#pragma unroll
        for (int ks = 0; ks < 4; ks++) {
            uint32_t a0, a1, a2, a3;
            LDSM_X4(a0, a1, a2, a3, aP + ks * 32);
#pragma unroll
            for (int p = 0; p < 4; p++) {
                uint32_t b0, b1, b2, b3;
                LDSM_X4(b0, b1, b2, b3, bV + (p * 16 * AS + ks * 16) * 2);
                MMA_F16(o[2 * p],     a0, a1, a2, a3, b0, b1);
                MMA_F16(o[2 * p + 1], a0, a1, a2, a3, b2, b3);
            }
        }
    }

    // ---- epilogue: fp16 into g_Ah ----
    const float inv0 = 1.0f / l0;
    const float inv1 = 1.0f / l1;
    const size_t row0 = (size_t)(b * SQ_TOT + qt * 128 + wid * 16 + g);
    __half* o0 = O + row0 * DMODEL + h * DHEAD + 2 * t;
    __half* o1 = o0 + 8 * DMODEL;
#pragma unroll
    for (int dt = 0; dt < 8; dt++) {
        *(__half2*)(o0 + dt * 8) = __floats2half2_rn(o[dt][0] * inv0, o[dt][1] * inv0);
        *(__half2*)(o1 + dt * 8) = __floats2half2_rn(o[dt][2] * inv1, o[dt][3] * inv1);
    }
}

// ===========================================================================
extern "C" void kernel_launch(void* const* d_in, const int* in_sizes, int n_in,
                              void* d_out, int out_size)
{
    const float* x   = (const float*)d_in[0];
    const float* ctx = (const float*)d_in[1];
    const float* Wq  = (const float*)d_in[2];
    const float* Wk  = (const float*)d_in[3];
    const float* Wv  = (const float*)d_in[4];
    const float* Wo  = (const float*)d_in[5];
    const float* bo  = (const float*)d_in[6];
    float* out = (float*)d_out;

    __half *xH, *cH, *wqH, *wkH, *wvH, *woH, *qh, *kh, *vh, *ah;
    cudaGetSymbolAddress((void**)&xH,  g_xH);
    cudaGetSymbolAddress((void**)&cH,  g_cH);
    cudaGetSymbolAddress((void**)&wqH, g_wqH);
    cudaGetSymbolAddress((void**)&wkH, g_wkH);
    cudaGetSymbolAddress((void**)&wvH, g_wvH);
    cudaGetSymbolAddress((void**)&woH, g_woH);
    cudaGetSymbolAddress((void**)&qh,  g_Qh);
    cudaGetSymbolAddress((void**)&kh,  g_Kh);
    cudaGetSymbolAddress((void**)&vh,  g_Vh);
    cudaGetSymbolAddress((void**)&ah,  g_Ah);

    cudaFuncSetAttribute(gemm_f16,
                         cudaFuncAttributeMaxDynamicSharedMemorySize, GP_SMEM);
    cudaFuncSetAttribute(attn_f16,
                         cudaFuncAttributeMaxDynamicSharedMemorySize, ATT_SMEM);

    const int M_Q = BATCH * SQ_TOT;   // 12288
    const int M_KV = BATCH * SK_TOT;  // 2048
    const int NW = DMODEL * DMODEL;

    cvt_f16<<<(M_Q * DMODEL / 8 + 255) / 256, 256>>>(x, xH, M_Q * DMODEL);
    cvt_f16<<<(M_KV * DMODEL / 8 + 255) / 256, 256>>>(ctx, cH, M_KV * DMODEL);
    cvt_f16<<<(NW / 8 + 255) / 256, 256>>>(Wq, wqH, NW);
    cvt_f16<<<(NW / 8 + 255) / 256, 256>>>(Wk, wkH, NW);
    cvt_f16<<<(NW / 8 + 255) / 256, 256>>>(Wv, wvH, NW);
    cvt_f16<<<(NW / 8 + 255) / 256, 256>>>(Wo, woH, NW);

    gemm_f16<<<dim3(DMODEL / 128, M_Q / 128), 256, GP_SMEM>>>(
        xH, wqH, nullptr, qh, M_Q, DMODEL, DMODEL, nullptr, 0.125f, 1);
    gemm_f16<<<dim3(DMODEL / 128, M_KV / 128), 256, GP_SMEM>>>(
        cH, wkH, nullptr, kh, M_KV, DMODEL, DMODEL, nullptr, 1.0f, 1);
    gemm_f16<<<dim3(DMODEL / 128, M_KV / 128), 256, GP_SMEM>>>(
        cH, wvH, nullptr, vh, M_KV, DMODEL, DMODEL, nullptr, 1.0f, 2);

    attn_f16<<<dim3(SQ_TOT / 128, NHEADS, BATCH), 256, ATT_SMEM>>>(qh, kh, vh, ah);

    gemm_f16<<<dim3(DMODEL / 128, M_Q / 128), 256, GP_SMEM>>>(
        ah, woH, out, nullptr, M_Q, DMODEL, DMODEL, bo, 1.0f, 0);
}

// round 7
// speedup vs baseline: 4.6209x; 1.1452x over previous
#include <cuda_runtime.h>
#include <cuda_fp16.h>
#include <cstdint>

// Problem constants
#define DMODEL 1024
#define NHEADS 16
#define DHEAD  64
#define SQ_TOT 6144   // per batch
#define SK_TOT 1024
#define BATCH  2

// Scratch (allocation-free rule: __device__ globals), all fp16.
__device__ __half g_xH[BATCH * SQ_TOT * DMODEL];
__device__ __half g_cH[BATCH * SK_TOT * DMODEL];
__device__ __half g_wqH[DMODEL * DMODEL];
__device__ __half g_wkH[DMODEL * DMODEL];
__device__ __half g_wvH[DMODEL * DMODEL];
__device__ __half g_woH[DMODEL * DMODEL];
__device__ __half g_Qh[BATCH * SQ_TOT * DMODEL];   // pre-scaled by 0.125*log2(e)
__device__ __half g_Kh[BATCH * SK_TOT * DMODEL];
__device__ __half g_Vh[BATCH * NHEADS * DHEAD * SK_TOT]; // [b][h][d][key]
__device__ __half g_Ah[BATCH * SQ_TOT * DMODEL];

__device__ __forceinline__ uint32_t smem_u32(const void* p) {
    uint32_t a;
    asm("{ .reg .u64 t; cvta.to.shared.u64 t, %1; cvt.u32.u64 %0, t; }"
        : "=r"(a) : "l"(p));
    return a;
}

#define CP16(dst, src) \
    asm volatile("cp.async.cg.shared.global [%0], [%1], 16;" :: "r"(dst), "l"(src))
#define CP_COMMIT() asm volatile("cp.async.commit_group;" ::: "memory")
#define CP_WAIT(n)  asm volatile("cp.async.wait_group %0;" :: "n"(n) : "memory")

#define LDSM_X4(r0, r1, r2, r3, addr) \
    asm volatile("ldmatrix.sync.aligned.m8n8.x4.shared.b16 {%0,%1,%2,%3}, [%4];" \
        : "=r"(r0), "=r"(r1), "=r"(r2), "=r"(r3) : "r"(addr))

#define MMA_F16(d, a0, a1, a2, a3, b0, b1) \
    asm volatile( \
        "mma.sync.aligned.m16n8k16.row.col.f32.f16.f16.f32 " \
        "{%0,%1,%2,%3}, {%4,%5,%6,%7}, {%8,%9}, {%0,%1,%2,%3};" \
        : "+f"((d)[0]), "+f"((d)[1]), "+f"((d)[2]), "+f"((d)[3]) \
        : "r"(a0), "r"(a1), "r"(a2), "r"(a3), "r"(b0), "r"(b1))

// ===========================================================================
// fp32 -> fp16 conversion
// ===========================================================================
__global__ void cvt_f16(const float* __restrict__ in, __half* __restrict__ out, int n)
{
    int i = (blockIdx.x * blockDim.x + threadIdx.x) * 8;
    if (i < n) {
        float4 a = *(const float4*)(in + i);
        float4 b = *(const float4*)(in + i + 4);
        __half2* o = (__half2*)(out + i);
        o[0] = __floats2half2_rn(a.x, a.y);
        o[1] = __floats2half2_rn(a.z, a.w);
        o[2] = __floats2half2_rn(b.x, b.y);
        o[3] = __floats2half2_rn(b.z, b.w);
    }
}

// 4 arrays in one launch (the weights)
__global__ void cvt_f16x4(
    const float* __restrict__ i0, __half* __restrict__ o0,
    const float* __restrict__ i1, __half* __restrict__ o1,
    const float* __restrict__ i2, __half* __restrict__ o2,
    const float* __restrict__ i3, __half* __restrict__ o3, int n)
{
    const float* in; __half* out;
    switch (blockIdx.y) {
        case 0: in = i0; out = o0; break;
        case 1: in = i1; out = o1; break;
        case 2: in = i2; out = o2; break;
        default: in = i3; out = o3; break;
    }
    int i = (blockIdx.x * blockDim.x + threadIdx.x) * 8;
    if (i < n) {
        float4 a = *(const float4*)(in + i);
        float4 b = *(const float4*)(in + i + 4);
        __half2* o = (__half2*)(out + i);
        o[0] = __floats2half2_rn(a.x, a.y);
        o[1] = __floats2half2_rn(a.z, a.w);
        o[2] = __floats2half2_rn(b.x, b.y);
        o[3] = __floats2half2_rn(b.z, b.w);
    }
}

// ===========================================================================
// fp16 mma GEMM NT. CTA 128x128, 8 warps (2M x 4N), warp 64x32, KC=32,
// 3-stage cp.async, smem stride 40 halves.
// Modes: 0 = fp32 out + bias; 1 = fp16 out scaled;
//        3 = merged KV: n-tiles [0,N/2) -> Ch (K layout), [N/2,N) -> Ch2
//            (V transposed to [b][h][d][key]); B2 is the second weight.
// ===========================================================================
#define KCH 32
#define SAH 40
#define NST 3
#define GSTAGE (128 * SAH)
#define GP_SMEM (2 * NST * GSTAGE * 2)

__global__ __launch_bounds__(256) void gemm_f16(
    const __half* __restrict__ A, const __half* __restrict__ B,
    const __half* __restrict__ B2,
    float* __restrict__ Cf, __half* __restrict__ Ch, __half* __restrict__ Ch2,
    int M, int N, int K, const float* __restrict__ bias, float scale, int mode)
{
    extern __shared__ __half sh[];
    __half* As = sh;
    __half* Bs = sh + NST * GSTAGE;

    const int tid = threadIdx.x;
    const int wid = tid >> 5;
    const int lane = tid & 31;
    const int g = lane >> 2;
    const int t = lane & 3;
    const int wm = (wid & 1) * 64;
    const int wn = (wid >> 1) * 32;
    const int bm = blockIdx.y * 128;
    const int bn = blockIdx.x * 128;

    // KV-merge routing
    const __half* Bptr = B;
    int bnOut = bn;
    int Nout = N;
    bool isV = false;
    if (mode == 3) {
        Nout = N >> 1;
        if (bn >= Nout) { Bptr = B2; bnOut = bn - Nout; isV = true; }
    }

    const int lrow = tid >> 1;
    const int lc = (tid & 1) * 2;
    const __half* Ag = A + (size_t)(bm + lrow) * K + lc * 8;
    const __half* Bg = Bptr + (size_t)(bnOut + lrow) * K + lc * 8;
    const uint32_t sA0 = smem_u32(As) + (lrow * SAH + lc * 8) * 2;
    const uint32_t sB0 = smem_u32(Bs) + (lrow * SAH + lc * 8) * 2;
    const uint32_t stB = GSTAGE * 2;

    const int arow = (lane & 7) + ((lane >> 3) & 1) * 8;
    const int acol = (lane >> 4) * 8;
    const int brow = (lane & 7) + (lane >> 4) * 8;
    const int bcol = ((lane >> 3) & 1) * 8;
    const uint32_t aBase = smem_u32(As) + ((wm + arow) * SAH + acol) * 2;
    const uint32_t bBase = smem_u32(Bs) + ((wn + brow) * SAH + bcol) * 2;

    float acc[4][4][4];
#pragma unroll
    for (int i = 0; i < 4; i++)
#pragma unroll
        for (int j = 0; j < 4; j++)
#pragma unroll
            for (int r = 0; r < 4; r++) acc[i][j][r] = 0.0f;

    const int NC = K / KCH;

#pragma unroll
    for (int c = 0; c < NST - 1; c++) {
        CP16(sA0 + c * stB,      Ag + (size_t)c * KCH);
        CP16(sA0 + c * stB + 16, Ag + (size_t)c * KCH + 8);
        CP16(sB0 + c * stB,      Bg + (size_t)c * KCH);
        CP16(sB0 + c * stB + 16, Bg + (size_t)c * KCH + 8);
        CP_COMMIT();
    }

    for (int c = 0; c < NC; c++) {
        const int st = c % NST;
        CP_WAIT(NST - 2);
        __syncthreads();

        {
            const int cn = c + NST - 1;
            if (cn < NC) {
                const int sn = cn % NST;
                CP16(sA0 + sn * stB,      Ag + (size_t)cn * KCH);
                CP16(sA0 + sn * stB + 16, Ag + (size_t)cn * KCH + 8);
                CP16(sB0 + sn * stB,      Bg + (size_t)cn * KCH);
                CP16(sB0 + sn * stB + 16, Bg + (size_t)cn * KCH + 8);
            }
            CP_COMMIT();
        }

        const uint32_t aSt = aBase + st * stB;
        const uint32_t bSt = bBase + st * stB;
#pragma unroll
        for (int ks = 0; ks < 2; ks++) {
            uint32_t a[4][4];
#pragma unroll
            for (int mt = 0; mt < 4; mt++)
                LDSM_X4(a[mt][0], a[mt][1], a[mt][2], a[mt][3],
                        aSt + (mt * 16 * SAH + ks * 16) * 2);
#pragma unroll
            for (int p = 0; p < 2; p++) {
                uint32_t b0, b1, b2, b3;
                LDSM_X4(b0, b1, b2, b3, bSt + (p * 16 * SAH + ks * 16) * 2);
#pragma unroll
                for (int mt = 0; mt < 4; mt++) {
                    MMA_F16(acc[mt][2 * p],     a[mt][0], a[mt][1], a[mt][2], a[mt][3], b0, b1);
                    MMA_F16(acc[mt][2 * p + 1], a[mt][0], a[mt][1], a[mt][2], a[mt][3], b2, b3);
                }
            }
        }
        __syncthreads();
    }

    // Epilogue
#pragma unroll
    for (int mt = 0; mt < 4; mt++) {
#pragma unroll
        for (int nt = 0; nt < 4; nt++) {
            const int row = bm + wm + mt * 16 + g;
            const int col = bnOut + wn + nt * 8 + 2 * t;
            float c0 = acc[mt][nt][0], c1 = acc[mt][nt][1];
            float c2 = acc[mt][nt][2], c3 = acc[mt][nt][3];
            if (mode == 0) {
                float2 bv = *(const float2*)&bias[col];
                *(float2*)&Cf[(size_t)row * N + col] = make_float2(c0 + bv.x, c1 + bv.y);
                *(float2*)&Cf[(size_t)(row + 8) * N + col] = make_float2(c2 + bv.x, c3 + bv.y);
            } else if (mode == 1) {
                *(__half2*)&Ch[(size_t)row * N + col] =
                    __floats2half2_rn(c0 * scale, c1 * scale);
                *(__half2*)&Ch[(size_t)(row + 8) * N + col] =
                    __floats2half2_rn(c2 * scale, c3 * scale);
            } else if (!isV) {
                // K half of merged KV
                *(__half2*)&Ch[(size_t)row * Nout + col] = __floats2half2_rn(c0, c1);
                *(__half2*)&Ch[(size_t)(row + 8) * Nout + col] = __floats2half2_rn(c2, c3);
            } else {
                // V half: row = b*1024+key, col = h*64+d -> [b][h][d][key]
                const int b = row >> 10, key = row & 1023;
                const int h = col >> 6, d = col & 63;
                __half* base = Ch2 + ((size_t)((b * NHEADS + h) * DHEAD + d)) * SK_TOT;
                base[key]              = __float2half(c0);
                base[SK_TOT + key]     = __float2half(c1);
                base[key + 8]          = __float2half(c2);
                base[SK_TOT + key + 8] = __float2half(c3);
            }
        }
    }
}

// ===========================================================================
// Flash attention, fp16 mma + ldmatrix, double-buffered K/V tiles,
// exp2-domain softmax (log2(e) folded into Q scale).
// Block: 128 queries x one (b,h); 8 warps; warp w owns rows [16w,16w+16).
// ===========================================================================
#define AS 72
#define NKT (SK_TOT / 64)
#define ATT_SMEM ((128 + 2 * 64 + 2 * 64 + 128) * AS * 2)

__global__ __launch_bounds__(256) void attn_f16(
    const __half* __restrict__ Q, const __half* __restrict__ K,
    const __half* __restrict__ V, __half* __restrict__ O)
{
    extern __shared__ __half sma[];
    __half* sQ  = sma;                   // [128][AS]
    __half* sKb = sQ + 128 * AS;         // 2 x [64][AS]
    __half* sVb = sKb + 2 * 64 * AS;     // 2 x [64][AS]
    __half* sP  = sVb + 2 * 64 * AS;     // [128][AS]
    const uint32_t bufBytes = 64 * AS * 2;

    const int b = blockIdx.z;
    const int h = blockIdx.y;
    const int qt = blockIdx.x;

    const int tid = threadIdx.x;
    const int wid = tid >> 5;
    const int lane = tid & 31;
    const int g = lane >> 2;
    const int t = lane & 3;

    const uint32_t sQa = smem_u32(sQ);
    const uint32_t sKa = smem_u32(sKb);
    const uint32_t sVa = smem_u32(sVb);

    // Q tile (128x64h)
    {
        const int row = tid >> 1, c0 = (tid & 1) * 4;
        const __half* qg = Q + (size_t)(b * SQ_TOT + qt * 128 + row) * DMODEL
                             + h * DHEAD + c0 * 8;
        const uint32_t qd = sQa + (row * AS + c0 * 8) * 2;
#pragma unroll
        for (int i = 0; i < 4; i++) CP16(qd + i * 16, qg + i * 8);
    }

    // K/V tile issue
    const int lrow = tid >> 2;
    const int lc = (tid & 3) * 2;
    const __half* kgB = K + (size_t)(b * SK_TOT + lrow) * DMODEL + h * DHEAD + lc * 8;
    const __half* vgB = V + ((size_t)((b * NHEADS + h) * DHEAD + lrow)) * SK_TOT + lc * 8;
    const uint32_t kd0 = sKa + (lrow * AS + lc * 8) * 2;
    const uint32_t vd0 = sVa + (lrow * AS + lc * 8) * 2;

#define ISSUE_KV(kt, buf) do { \
        const __half* kg_ = kgB + (size_t)(kt) * 64 * DMODEL; \
        const __half* vg_ = vgB + (kt) * 64; \
        const uint32_t kd_ = kd0 + (buf) * bufBytes; \
        const uint32_t vd_ = vd0 + (buf) * bufBytes; \
        CP16(kd_, kg_);      CP16(kd_ + 16, kg_ + 8); \
        CP16(vd_, vg_);      CP16(vd_ + 16, vg_ + 8); \
    } while (0)

    ISSUE_KV(0, 0); CP_COMMIT();   // group: Q + tile0
    ISSUE_KV(1, 1); CP_COMMIT();   // group: tile1

    // ldmatrix per-lane bases (buffer 0)
    const int arow = (lane & 7) + ((lane >> 3) & 1) * 8;
    const int acol = (lane >> 4) * 8;
    const int brow = (lane & 7) + (lane >> 4) * 8;
    const int bcol = ((lane >> 3) & 1) * 8;
    const uint32_t aQ = sQa + ((wid * 16 + arow) * AS + acol) * 2;
    const uint32_t aP = smem_u32(sP) + ((wid * 16 + arow) * AS + acol) * 2;
    const uint32_t bK0 = sKa + (brow * AS + bcol) * 2;
    const uint32_t bV0 = sVa + (brow * AS + bcol) * 2;

    float m0 = -1e30f, m1 = -1e30f, l0 = 0.0f, l1 = 0.0f;
    float o[8][4];
#pragma unroll
    for (int dt = 0; dt < 8; dt++)
#pragma unroll
        for (int r = 0; r < 4; r++) o[dt][r] = 0.0f;

    for (int kt = 0; kt < NKT; kt++) {
        if (kt < NKT - 1) { CP_WAIT(1); } else { CP_WAIT(0); }
        __syncthreads();

        const uint32_t bOff = (kt & 1) * bufBytes;
        const uint32_t bK = bK0 + bOff;
        const uint32_t bV = bV0 + bOff;

        // ---- S = Q @ K^T ----
        float s[8][4];
#pragma unroll
        for (int nt = 0; nt < 8; nt++)
#pragma unroll
            for (int r = 0; r < 4; r++) s[nt][r] = 0.0f;

#pragma unroll
        for (int ks = 0; ks < 4; ks++) {
            uint32_t a0, a1, a2, a3;
            LDSM_X4(a0, a1, a2, a3, aQ + ks * 32);
#pragma unroll
            for (int p = 0; p < 4; p++) {
                uint32_t b0, b1, b2, b3;
                LDSM_X4(b0, b1, b2, b3, bK + (p * 16 * AS + ks * 16) * 2);
                MMA_F16(s[2 * p],     a0, a1, a2, a3, b0, b1);
                MMA_F16(s[2 * p + 1], a0, a1, a2, a3, b2, b3);
            }
        }

        // ---- online softmax (exp2 domain) ----
        float ml0 = -1e30f, ml1 = -1e30f;
#pragma unroll
        for (int nt = 0; nt < 8; nt++) {
            ml0 = fmaxf(ml0, fmaxf(s[nt][0], s[nt][1]));
            ml1 = fmaxf(ml1, fmaxf(s[nt][2], s[nt][3]));
        }
        ml0 = fmaxf(ml0, __shfl_xor_sync(0xffffffffu, ml0, 1));
        ml0 = fmaxf(ml0, __shfl_xor_sync(0xffffffffu, ml0, 2));
        ml1 = fmaxf(ml1, __shfl_xor_sync(0xffffffffu, ml1, 1));
        ml1 = fmaxf(ml1, __shfl_xor_sync(0xffffffffu, ml1, 2));

        const float mn0 = fmaxf(m0, ml0);
        const float mn1 = fmaxf(m1, ml1);
        const float al0 = exp2f(m0 - mn0);
        const float al1 = exp2f(m1 - mn1);
        m0 = mn0; m1 = mn1;

        float rs0 = 0.0f, rs1 = 0.0f;
        __half2* pr0 = (__half2*)&sP[(wid * 16 + g) * AS + 2 * t];
        __half2* pr1 = (__half2*)&sP[(wid * 16 + 8 + g) * AS + 2 * t];
#pragma unroll
        for (int nt = 0; nt < 8; nt++) {
            float p00 = exp2f(s[nt][0] - mn0);
            float p01 = exp2f(s[nt][1] - mn0);
            float p10 = exp2f(s[nt][2] - mn1);
            float p11 = exp2f(s[nt][3] - mn1);
            rs0 += p00 + p01;
            rs1 += p10 + p11;
            pr0[nt * 4] = __floats2half2_rn(p00, p01);
            pr1[nt * 4] = __floats2half2_rn(p10, p11);
        }
        rs0 += __shfl_xor_sync(0xffffffffu, rs0, 1);
        rs0 += __shfl_xor_sync(0xffffffffu, rs0, 2);
        rs1 += __shfl_xor_sync(0xffffffffu, rs1, 1);
        rs1 += __shfl_xor_sync(0xffffffffu, rs1, 2);
        l0 = l0 * al0 + rs0;
        l1 = l1 * al1 + rs1;
#pragma unroll
        for (int dt = 0; dt < 8; dt++) {
            o[dt][0] *= al0; o[dt][1] *= al0;
            o[dt][2] *= al1; o[dt][3] *= al1;
        }
        __syncwarp();   // this warp's sP rows fully written

        // ---- O += P @ V ----
#pragma unroll
        for (int ks = 0; ks < 4; ks++) {
            uint32_t a0, a1, a2, a3;
            LDSM_X4(a0, a1, a2, a3, aP + ks * 32);
#pragma unroll
            for (int p = 0; p < 4; p++) {
                uint32_t b0, b1, b2, b3;
                LDSM_X4(b0, b1, b2, b3, bV + (p * 16 * AS + ks * 16) * 2);
                MMA_F16(o[2 * p],     a0, a1, a2, a3, b0, b1);
                MMA_F16(o[2 * p + 1], a0, a1, a2, a3, b2, b3);
            }
        }

        __syncthreads();   // everyone done reading buf (kt&1) before refill
        if (kt + 2 < NKT) { ISSUE_KV(kt + 2, kt & 1); CP_COMMIT(); }
    }

    // ---- epilogue ----
    const float inv0 = 1.0f / l0;
    const float inv1 = 1.0f / l1;
    const size_t row0 = (size_t)(b * SQ_TOT + qt * 128 + wid * 16 + g);
    __half* o0 = O + row0 * DMODEL + h * DHEAD + 2 * t;
    __half* o1 = o0 + 8 * DMODEL;
#pragma unroll
    for (int dt = 0; dt < 8; dt++) {
        *(__half2*)(o0 + dt * 8) = __floats2half2_rn(o[dt][0] * inv0, o[dt][1] * inv0);
        *(__half2*)(o1 + dt * 8) = __floats2half2_rn(o[dt][2] * inv1, o[dt][3] * inv1);
    }
}

// ===========================================================================
extern "C" void kernel_launch(void* const* d_in, const int* in_sizes, int n_in,
                              void* d_out, int out_size)
{
    const float* x   = (const float*)d_in[0];
    const float* ctx = (const float*)d_in[1];
    const float* Wq  = (const float*)d_in[2];
    const float* Wk  = (const float*)d_in[3];
    const float* Wv  = (const float*)d_in[4];
    const float* Wo  = (const float*)d_in[5];
    const float* bo  = (const float*)d_in[6];
    float* out = (float*)d_out;

    __half *xH, *cH, *wqH, *wkH, *wvH, *woH, *qh, *kh, *vh, *ah;
    cudaGetSymbolAddress((void**)&xH,  g_xH);
    cudaGetSymbolAddress((void**)&cH,  g_cH);
    cudaGetSymbolAddress((void**)&wqH, g_wqH);
    cudaGetSymbolAddress((void**)&wkH, g_wkH);
    cudaGetSymbolAddress((void**)&wvH, g_wvH);
    cudaGetSymbolAddress((void**)&woH, g_woH);
    cudaGetSymbolAddress((void**)&qh,  g_Qh);
    cudaGetSymbolAddress((void**)&kh,  g_Kh);
    cudaGetSymbolAddress((void**)&vh,  g_Vh);
    cudaGetSymbolAddress((void**)&ah,  g_Ah);

    cudaFuncSetAttribute(gemm_f16,
                         cudaFuncAttributeMaxDynamicSharedMemorySize, GP_SMEM);
    cudaFuncSetAttribute(attn_f16,
                         cudaFuncAttributeMaxDynamicSharedMemorySize, ATT_SMEM);

    const int M_Q = BATCH * SQ_TOT;   // 12288
    const int M_KV = BATCH * SK_TOT;  // 2048
    const int NW = DMODEL * DMODEL;

    cvt_f16<<<(M_Q * DMODEL / 8 + 255) / 256, 256>>>(x, xH, M_Q * DMODEL);
    cvt_f16<<<(M_KV * DMODEL / 8 + 255) / 256, 256>>>(ctx, cH, M_KV * DMODEL);
    cvt_f16x4<<<dim3((NW / 8 + 255) / 256, 4), 256>>>(
        Wq, wqH, Wk, wkH, Wv, wvH, Wo, woH, NW);

    const float QSCALE = 0.125f * 1.44269504088896341f;  // 1/sqrt(64) * log2(e)

    gemm_f16<<<dim3(DMODEL / 128, M_Q / 128), 256, GP_SMEM>>>(
        xH, wqH, nullptr, nullptr, qh, nullptr,
        M_Q, DMODEL, DMODEL, nullptr, QSCALE, 1);
    // merged K+V projection: N = 2048 logical
    gemm_f16<<<dim3(2 * DMODEL / 128, M_KV / 128), 256, GP_SMEM>>>(
        cH, wkH, wvH, nullptr, kh, vh,
        M_KV, 2 * DMODEL, DMODEL, nullptr, 1.0f, 3);

    attn_f16<<<dim3(SQ_TOT / 128, NHEADS, BATCH), 256, ATT_SMEM>>>(qh, kh, vh, ah);

    gemm_f16<<<dim3(DMODEL / 128, M_Q / 128), 256, GP_SMEM>>>(
        ah, woH, nullptr, out, nullptr, nullptr,
        M_Q, DMODEL, DMODEL, bo, 1.0f, 0);
}

// round 8
// speedup vs baseline: 7.5167x; 1.6267x over previous
#include <cuda_runtime.h>
#include <cuda_fp16.h>
#include <cstdint>

// Problem constants
#define DMODEL 1024
#define NHEADS 16
#define DHEAD  64
#define SQ_TOT 6144   // per batch
#define SK_TOT 1024
#define BATCH  2

// Scratch (allocation-free rule: __device__ globals), all fp16.
__device__ __half g_xH[BATCH * SQ_TOT * DMODEL];
__device__ __half g_cH[BATCH * SK_TOT * DMODEL];
__device__ __half g_wqH[DMODEL * DMODEL];
__device__ __half g_wkH[DMODEL * DMODEL];
__device__ __half g_wvH[DMODEL * DMODEL];
__device__ __half g_woH[DMODEL * DMODEL];
__device__ __half g_Qh[BATCH * SQ_TOT * DMODEL];   // pre-scaled by 0.125*log2(e)
__device__ __half g_Kh[BATCH * SK_TOT * DMODEL];
__device__ __half g_Vh[BATCH * NHEADS * DHEAD * SK_TOT]; // [b][h][d][key]
__device__ __half g_Ah[BATCH * SQ_TOT * DMODEL];

__device__ __forceinline__ uint32_t smem_u32(const void* p) {
    uint32_t a;
    asm("{ .reg .u64 t; cvta.to.shared.u64 t, %1; cvt.u32.u64 %0, t; }"
        : "=r"(a) : "l"(p));
    return a;
}

__device__ __forceinline__ uint32_t packh2(float a, float b) {
    __half2 h = __floats2half2_rn(a, b);
    return *reinterpret_cast<uint32_t*>(&h);
}

#define CP16(dst, src) \
    asm volatile("cp.async.cg.shared.global [%0], [%1], 16;" :: "r"(dst), "l"(src))
#define CP_COMMIT() asm volatile("cp.async.commit_group;" ::: "memory")
#define CP_WAIT(n)  asm volatile("cp.async.wait_group %0;" :: "n"(n) : "memory")

#define LDSM_X4(r0, r1, r2, r3, addr) \
    asm volatile("ldmatrix.sync.aligned.m8n8.x4.shared.b16 {%0,%1,%2,%3}, [%4];" \
        : "=r"(r0), "=r"(r1), "=r"(r2), "=r"(r3) : "r"(addr))

#define MMA_F16(d, a0, a1, a2, a3, b0, b1) \
    asm volatile( \
        "mma.sync.aligned.m16n8k16.row.col.f32.f16.f16.f32 " \
        "{%0,%1,%2,%3}, {%4,%5,%6,%7}, {%8,%9}, {%0,%1,%2,%3};" \
        : "+f"((d)[0]), "+f"((d)[1]), "+f"((d)[2]), "+f"((d)[3]) \
        : "r"(a0), "r"(a1), "r"(a2), "r"(a3), "r"(b0), "r"(b1))

// ===========================================================================
// fp32 -> fp16 conversion
// ===========================================================================
__global__ void cvt_f16(const float* __restrict__ in, __half* __restrict__ out, int n)
{
    int i = (blockIdx.x * blockDim.x + threadIdx.x) * 8;
    if (i < n) {
        float4 a = *(const float4*)(in + i);
        float4 b = *(const float4*)(in + i + 4);
        __half2* o = (__half2*)(out + i);
        o[0] = __floats2half2_rn(a.x, a.y);
        o[1] = __floats2half2_rn(a.z, a.w);
        o[2] = __floats2half2_rn(b.x, b.y);
        o[3] = __floats2half2_rn(b.z, b.w);
    }
}

__global__ void cvt_f16x4(
    const float* __restrict__ i0, __half* __restrict__ o0,
    const float* __restrict__ i1, __half* __restrict__ o1,
    const float* __restrict__ i2, __half* __restrict__ o2,
    const float* __restrict__ i3, __half* __restrict__ o3, int n)
{
    const float* in; __half* out;
    switch (blockIdx.y) {
        case 0: in = i0; out = o0; break;
        case 1: in = i1; out = o1; break;
        case 2: in = i2; out = o2; break;
        default: in = i3; out = o3; break;
    }
    int i = (blockIdx.x * blockDim.x + threadIdx.x) * 8;
    if (i < n) {
        float4 a = *(const float4*)(in + i);
        float4 b = *(const float4*)(in + i + 4);
        __half2* o = (__half2*)(out + i);
        o[0] = __floats2half2_rn(a.x, a.y);
        o[1] = __floats2half2_rn(a.z, a.w);
        o[2] = __floats2half2_rn(b.x, b.y);
        o[3] = __floats2half2_rn(b.z, b.w);
    }
}

// ===========================================================================
// fp16 mma GEMM NT. CTA 128x128, 8 warps (2M x 4N), warp 64x32, KC=32,
// 3-stage cp.async, ONE barrier per mainloop iteration.
// Modes: 0 = fp32 out + bias; 1 = fp16 out scaled;
//        3 = merged KV (K half -> Ch, V half -> Ch2 transposed [b][h][d][key]).
// ===========================================================================
#define KCH 32
#define SAH 40
#define NST 3
#define GSTAGE (128 * SAH)
#define GP_SMEM (2 * NST * GSTAGE * 2)

__global__ __launch_bounds__(256) void gemm_f16(
    const __half* __restrict__ A, const __half* __restrict__ B,
    const __half* __restrict__ B2,
    float* __restrict__ Cf, __half* __restrict__ Ch, __half* __restrict__ Ch2,
    int M, int N, int K, const float* __restrict__ bias, float scale, int mode)
{
    extern __shared__ __half sh[];
    __half* As = sh;
    __half* Bs = sh + NST * GSTAGE;

    const int tid = threadIdx.x;
    const int wid = tid >> 5;
    const int lane = tid & 31;
    const int g = lane >> 2;
    const int t = lane & 3;
    const int wm = (wid & 1) * 64;
    const int wn = (wid >> 1) * 32;
    const int bm = blockIdx.y * 128;
    const int bn = blockIdx.x * 128;

    const __half* Bptr = B;
    int bnOut = bn;
    int Nout = N;
    bool isV = false;
    if (mode == 3) {
        Nout = N >> 1;
        if (bn >= Nout) { Bptr = B2; bnOut = bn - Nout; isV = true; }
    }

    const int lrow = tid >> 1;
    const int lc = (tid & 1) * 2;
    const __half* Ag = A + (size_t)(bm + lrow) * K + lc * 8;
    const __half* Bg = Bptr + (size_t)(bnOut + lrow) * K + lc * 8;
    const uint32_t sA0 = smem_u32(As) + (lrow * SAH + lc * 8) * 2;
    const uint32_t sB0 = smem_u32(Bs) + (lrow * SAH + lc * 8) * 2;
    const uint32_t stB = GSTAGE * 2;

    const int arow = (lane & 7) + ((lane >> 3) & 1) * 8;
    const int acol = (lane >> 4) * 8;
    const int brow = (lane & 7) + (lane >> 4) * 8;
    const int bcol = ((lane >> 3) & 1) * 8;
    const uint32_t aBase = smem_u32(As) + ((wm + arow) * SAH + acol) * 2;
    const uint32_t bBase = smem_u32(Bs) + ((wn + brow) * SAH + bcol) * 2;

    float acc[4][4][4];
#pragma unroll
    for (int i = 0; i < 4; i++)
#pragma unroll
        for (int j = 0; j < 4; j++)
#pragma unroll
            for (int r = 0; r < 4; r++) acc[i][j][r] = 0.0f;

    const int NC = K / KCH;

#pragma unroll
    for (int c = 0; c < NST - 1; c++) {
        CP16(sA0 + c * stB,      Ag + (size_t)c * KCH);
        CP16(sA0 + c * stB + 16, Ag + (size_t)c * KCH + 8);
        CP16(sB0 + c * stB,      Bg + (size_t)c * KCH);
        CP16(sB0 + c * stB + 16, Bg + (size_t)c * KCH + 8);
        CP_COMMIT();
    }

    for (int c = 0; c < NC; c++) {
        const int st = c % NST;
        CP_WAIT(NST - 2);
        __syncthreads();      // single barrier: stage c ready AND stage (c-1) free

        {
            const int cn = c + NST - 1;
            if (cn < NC) {
                const int sn = cn % NST;
                CP16(sA0 + sn * stB,      Ag + (size_t)cn * KCH);
                CP16(sA0 + sn * stB + 16, Ag + (size_t)cn * KCH + 8);
                CP16(sB0 + sn * stB,      Bg + (size_t)cn * KCH);
                CP16(sB0 + sn * stB + 16, Bg + (size_t)cn * KCH + 8);
            }
            CP_COMMIT();
        }

        const uint32_t aSt = aBase + st * stB;
        const uint32_t bSt = bBase + st * stB;
#pragma unroll
        for (int ks = 0; ks < 2; ks++) {
            uint32_t a[4][4];
#pragma unroll
            for (int mt = 0; mt < 4; mt++)
                LDSM_X4(a[mt][0], a[mt][1], a[mt][2], a[mt][3],
                        aSt + (mt * 16 * SAH + ks * 16) * 2);
#pragma unroll
            for (int p = 0; p < 2; p++) {
                uint32_t b0, b1, b2, b3;
                LDSM_X4(b0, b1, b2, b3, bSt + (p * 16 * SAH + ks * 16) * 2);
#pragma unroll
                for (int mt = 0; mt < 4; mt++) {
                    MMA_F16(acc[mt][2 * p],     a[mt][0], a[mt][1], a[mt][2], a[mt][3], b0, b1);
                    MMA_F16(acc[mt][2 * p + 1], a[mt][0], a[mt][1], a[mt][2], a[mt][3], b2, b3);
                }
            }
        }
    }

#pragma unroll
    for (int mt = 0; mt < 4; mt++) {
#pragma unroll
        for (int nt = 0; nt < 4; nt++) {
            const int row = bm + wm + mt * 16 + g;
            const int col = bnOut + wn + nt * 8 + 2 * t;
            float c0 = acc[mt][nt][0], c1 = acc[mt][nt][1];
            float c2 = acc[mt][nt][2], c3 = acc[mt][nt][3];
            if (mode == 0) {
                float2 bv = *(const float2*)&bias[col];
                *(float2*)&Cf[(size_t)row * N + col] = make_float2(c0 + bv.x, c1 + bv.y);
                *(float2*)&Cf[(size_t)(row + 8) * N + col] = make_float2(c2 + bv.x, c3 + bv.y);
            } else if (mode == 1) {
                *(__half2*)&Ch[(size_t)row * N + col] =
                    __floats2half2_rn(c0 * scale, c1 * scale);
                *(__half2*)&Ch[(size_t)(row + 8) * N + col] =
                    __floats2half2_rn(c2 * scale, c3 * scale);
            } else if (!isV) {
                *(__half2*)&Ch[(size_t)row * Nout + col] = __floats2half2_rn(c0, c1);
                *(__half2*)&Ch[(size_t)(row + 8) * Nout + col] = __floats2half2_rn(c2, c3);
            } else {
                const int b = row >> 10, key = row & 1023;
                const int h = col >> 6, d = col & 63;
                __half* base = Ch2 + ((size_t)((b * NHEADS + h) * DHEAD + d)) * SK_TOT;
                base[key]              = __float2half(c0);
                base[SK_TOT + key]     = __float2half(c1);
                base[key + 8]          = __float2half(c2);
                base[SK_TOT + key + 8] = __float2half(c3);
            }
        }
    }
}

// ===========================================================================
// Flash attention: fp16 mma, P-in-registers (FA2 fragment trick), Q fragments
// hoisted, 3-buffer K/V cp.async pipeline, ONE barrier per key tile.
// Block: 128 queries x one (b,h); 8 warps; warp w owns rows [16w,16w+16).
// ===========================================================================
#define AS 72
#define NKT (SK_TOT / 64)
#define NBUF 3
#define ATT_SMEM ((128 + 2 * NBUF * 64) * AS * 2)

__global__ __launch_bounds__(256) void attn_f16(
    const __half* __restrict__ Q, const __half* __restrict__ K,
    const __half* __restrict__ V, __half* __restrict__ O)
{
    extern __shared__ __half sma[];
    __half* sQ  = sma;                     // [128][AS]
    __half* sKb = sQ + 128 * AS;           // NBUF x [64][AS]  (key rows x d)
    __half* sVb = sKb + NBUF * 64 * AS;    // NBUF x [64][AS]  (d rows x key)
    const uint32_t bufBytes = 64 * AS * 2;

    const int b = blockIdx.z;
    const int h = blockIdx.y;
    const int qt = blockIdx.x;

    const int tid = threadIdx.x;
    const int wid = tid >> 5;
    const int lane = tid & 31;
    const int g = lane >> 2;
    const int t = lane & 3;

    const uint32_t sQa = smem_u32(sQ);
    const uint32_t sKa = smem_u32(sKb);
    const uint32_t sVa = smem_u32(sVb);

    // Q tile (128x64h)
    {
        const int row = tid >> 1, c0 = (tid & 1) * 4;
        const __half* qg = Q + (size_t)(b * SQ_TOT + qt * 128 + row) * DMODEL
                             + h * DHEAD + c0 * 8;
        const uint32_t qd = sQa + (row * AS + c0 * 8) * 2;
#pragma unroll
        for (int i = 0; i < 4; i++) CP16(qd + i * 16, qg + i * 8);
    }

    const int lrow = tid >> 2;
    const int lc = (tid & 3) * 2;
    const __half* kgB = K + (size_t)(b * SK_TOT + lrow) * DMODEL + h * DHEAD + lc * 8;
    const __half* vgB = V + ((size_t)((b * NHEADS + h) * DHEAD + lrow)) * SK_TOT + lc * 8;
    const uint32_t kd0 = sKa + (lrow * AS + lc * 8) * 2;
    const uint32_t vd0 = sVa + (lrow * AS + lc * 8) * 2;

#define ISSUE_KV(kt, buf) do { \
        const __half* kg_ = kgB + (size_t)(kt) * 64 * DMODEL; \
        const __half* vg_ = vgB + (kt) * 64; \
        const uint32_t kd_ = kd0 + (buf) * bufBytes; \
        const uint32_t vd_ = vd0 + (buf) * bufBytes; \
        CP16(kd_, kg_);      CP16(kd_ + 16, kg_ + 8); \
        CP16(vd_, vg_);      CP16(vd_ + 16, vg_ + 8); \
    } while (0)

    ISSUE_KV(0, 0); CP_COMMIT();   // group 0: Q + tile0
    ISSUE_KV(1, 1); CP_COMMIT();   // group 1: tile1

    // ldmatrix per-lane bases
    const int arow = (lane & 7) + ((lane >> 3) & 1) * 8;
    const int acol = (lane >> 4) * 8;
    const int brow = (lane & 7) + (lane >> 4) * 8;
    const int bcol = ((lane >> 3) & 1) * 8;
    const uint32_t aQ = sQa + ((wid * 16 + arow) * AS + acol) * 2;
    const uint32_t bK0 = sKa + (brow * AS + bcol) * 2;
    const uint32_t bV0 = sVa + (brow * AS + bcol) * 2;

    // Q ready with group 0 -> hoist Q fragments into registers
    CP_WAIT(1);
    __syncthreads();
    uint32_t qf[4][4];
#pragma unroll
    for (int ks = 0; ks < 4; ks++)
        LDSM_X4(qf[ks][0], qf[ks][1], qf[ks][2], qf[ks][3], aQ + ks * 32);

    float m0 = -1e30f, m1 = -1e30f, l0 = 0.0f, l1 = 0.0f;
    float o[8][4];
#pragma unroll
    for (int dt = 0; dt < 8; dt++)
#pragma unroll
        for (int r = 0; r < 4; r++) o[dt][r] = 0.0f;

    for (int kt = 0; kt < NKT; kt++) {
        if (kt > 0) {
            CP_WAIT(1);
            __syncthreads();   // tile kt ready; buf (kt-1)%3 fully consumed
        }
        // refill distance-2 buffer
        if (kt + 2 < NKT) ISSUE_KV(kt + 2, (kt + 2) % NBUF);
        CP_COMMIT();

        const uint32_t bOff = (kt % NBUF) * bufBytes;
        const uint32_t bK = bK0 + bOff;
        const uint32_t bV = bV0 + bOff;

        // ---- S = Q @ K^T ----
        float s[8][4];
#pragma unroll
        for (int nt = 0; nt < 8; nt++)
#pragma unroll
            for (int r = 0; r < 4; r++) s[nt][r] = 0.0f;

#pragma unroll
        for (int ks = 0; ks < 4; ks++) {
#pragma unroll
            for (int p = 0; p < 4; p++) {
                uint32_t b0, b1, b2, b3;
                LDSM_X4(b0, b1, b2, b3, bK + (p * 16 * AS + ks * 16) * 2);
                MMA_F16(s[2 * p],     qf[ks][0], qf[ks][1], qf[ks][2], qf[ks][3], b0, b1);
                MMA_F16(s[2 * p + 1], qf[ks][0], qf[ks][1], qf[ks][2], qf[ks][3], b2, b3);
            }
        }

        // ---- online softmax (exp2 domain), P packed into A-fragments ----
        float ml0 = -1e30f, ml1 = -1e30f;
#pragma unroll
        for (int nt = 0; nt < 8; nt++) {
            ml0 = fmaxf(ml0, fmaxf(s[nt][0], s[nt][1]));
            ml1 = fmaxf(ml1, fmaxf(s[nt][2], s[nt][3]));
        }
        ml0 = fmaxf(ml0, __shfl_xor_sync(0xffffffffu, ml0, 1));
        ml0 = fmaxf(ml0, __shfl_xor_sync(0xffffffffu, ml0, 2));
        ml1 = fmaxf(ml1, __shfl_xor_sync(0xffffffffu, ml1, 1));
        ml1 = fmaxf(ml1, __shfl_xor_sync(0xffffffffu, ml1, 2));

        const float mn0 = fmaxf(m0, ml0);
        const float mn1 = fmaxf(m1, ml1);
        const float al0 = exp2f(m0 - mn0);
        const float al1 = exp2f(m1 - mn1);
        m0 = mn0; m1 = mn1;

        float rs0 = 0.0f, rs1 = 0.0f;
        uint32_t pa[4][4];
#pragma unroll
        for (int c = 0; c < 4; c++) {
            float p00 = exp2f(s[2 * c][0] - mn0);
            float p01 = exp2f(s[2 * c][1] - mn0);
            float p02 = exp2f(s[2 * c][2] - mn1);
            float p03 = exp2f(s[2 * c][3] - mn1);
            float p10 = exp2f(s[2 * c + 1][0] - mn0);
            float p11 = exp2f(s[2 * c + 1][1] - mn0);
            float p12 = exp2f(s[2 * c + 1][2] - mn1);
            float p13 = exp2f(s[2 * c + 1][3] - mn1);
            rs0 += p00 + p01 + p10 + p11;
            rs1 += p02 + p03 + p12 + p13;
            pa[c][0] = packh2(p00, p01);   // row g,   keys 16c+2t,+1
            pa[c][1] = packh2(p02, p03);   // row g+8, keys 16c+2t,+1
            pa[c][2] = packh2(p10, p11);   // row g,   keys 16c+8+2t,+1
            pa[c][3] = packh2(p12, p13);   // row g+8, keys 16c+8+2t,+1
        }
        rs0 += __shfl_xor_sync(0xffffffffu, rs0, 1);
        rs0 += __shfl_xor_sync(0xffffffffu, rs0, 2);
        rs1 += __shfl_xor_sync(0xffffffffu, rs1, 1);
        rs1 += __shfl_xor_sync(0xffffffffu, rs1, 2);
        l0 = l0 * al0 + rs0;
        l1 = l1 * al1 + rs1;
#pragma unroll
        for (int dt = 0; dt < 8; dt++) {
            o[dt][0] *= al0; o[dt][1] *= al0;
            o[dt][2] *= al1; o[dt][3] *= al1;
        }

        // ---- O += P @ V (P from registers) ----
#pragma unroll
        for (int c = 0; c < 4; c++) {
#pragma unroll
            for (int p = 0; p < 4; p++) {
                uint32_t b0, b1, b2, b3;
                LDSM_X4(b0, b1, b2, b3, bV + (p * 16 * AS + c * 16) * 2);
                MMA_F16(o[2 * p],     pa[c][0], pa[c][1], pa[c][2], pa[c][3], b0, b1);
                MMA_F16(o[2 * p + 1], pa[c][0], pa[c][1], pa[c][2], pa[c][3], b2, b3);
            }
        }
    }

    // ---- epilogue ----
    const float inv0 = 1.0f / l0;
    const float inv1 = 1.0f / l1;
    const size_t row0 = (size_t)(b * SQ_TOT + qt * 128 + wid * 16 + g);
    __half* o0 = O + row0 * DMODEL + h * DHEAD + 2 * t;
    __half* o1 = o0 + 8 * DMODEL;
#pragma unroll
    for (int dt = 0; dt < 8; dt++) {
        *(__half2*)(o0 + dt * 8) = __floats2half2_rn(o[dt][0] * inv0, o[dt][1] * inv0);
        *(__half2*)(o1 + dt * 8) = __floats2half2_rn(o[dt][2] * inv1, o[dt][3] * inv1);
    }
}

// ===========================================================================
extern "C" void kernel_launch(void* const* d_in, const int* in_sizes, int n_in,
                              void* d_out, int out_size)
{
    const float* x   = (const float*)d_in[0];
    const float* ctx = (const float*)d_in[1];
    const float* Wq  = (const float*)d_in[2];
    const float* Wk  = (const float*)d_in[3];
    const float* Wv  = (const float*)d_in[4];
    const float* Wo  = (const float*)d_in[5];
    const float* bo  = (const float*)d_in[6];
    float* out = (float*)d_out;

    __half *xH, *cH, *wqH, *wkH, *wvH, *woH, *qh, *kh, *vh, *ah;
    cudaGetSymbolAddress((void**)&xH,  g_xH);
    cudaGetSymbolAddress((void**)&cH,  g_cH);
    cudaGetSymbolAddress((void**)&wqH, g_wqH);
    cudaGetSymbolAddress((void**)&wkH, g_wkH);
    cudaGetSymbolAddress((void**)&wvH, g_wvH);
    cudaGetSymbolAddress((void**)&woH, g_woH);
    cudaGetSymbolAddress((void**)&qh,  g_Qh);
    cudaGetSymbolAddress((void**)&kh,  g_Kh);
    cudaGetSymbolAddress((void**)&vh,  g_Vh);
    cudaGetSymbolAddress((void**)&ah,  g_Ah);

    cudaFuncSetAttribute(gemm_f16,
                         cudaFuncAttributeMaxDynamicSharedMemorySize, GP_SMEM);
    cudaFuncSetAttribute(attn_f16,
                         cudaFuncAttributeMaxDynamicSharedMemorySize, ATT_SMEM);

    const int M_Q = BATCH * SQ_TOT;   // 12288
    const int M_KV = BATCH * SK_TOT;  // 2048
    const int NW = DMODEL * DMODEL;

    cvt_f16<<<(M_Q * DMODEL / 8 + 255) / 256, 256>>>(x, xH, M_Q * DMODEL);
    cvt_f16<<<(M_KV * DMODEL / 8 + 255) / 256, 256>>>(ctx, cH, M_KV * DMODEL);
    cvt_f16x4<<<dim3((NW / 8 + 255) / 256, 4), 256>>>(
        Wq, wqH, Wk, wkH, Wv, wvH, Wo, woH, NW);

    const float QSCALE = 0.125f * 1.44269504088896341f;  // 1/sqrt(64) * log2(e)

    gemm_f16<<<dim3(DMODEL / 128, M_Q / 128), 256, GP_SMEM>>>(
        xH, wqH, nullptr, nullptr, qh, nullptr,
        M_Q, DMODEL, DMODEL, nullptr, QSCALE, 1);
    gemm_f16<<<dim3(2 * DMODEL / 128, M_KV / 128), 256, GP_SMEM>>>(
        cH, wkH, wvH, nullptr, kh, vh,
        M_KV, 2 * DMODEL, DMODEL, nullptr, 1.0f, 3);

    attn_f16<<<dim3(SQ_TOT / 128, NHEADS, BATCH), 256, ATT_SMEM>>>(qh, kh, vh, ah);

    gemm_f16<<<dim3(DMODEL / 128, M_Q / 128), 256, GP_SMEM>>>(
        ah, woH, nullptr, out, nullptr, nullptr,
        M_Q, DMODEL, DMODEL, bo, 1.0f, 0);
}